// round 7
// baseline (speedup 1.0000x reference)
#include <cuda_runtime.h>
#include <cuda_fp16.h>
#include <math.h>
#include <stdint.h>

#define B_DIM 2
#define S_DIM 8192
#define E_DIM 128

// fp16 fragment-permuted scratch (uint4 = 4 x .b32 = 8 halves):
// g_Qp: per m-tile (16 q rows): [kk 0..7][lane] -> A-frag m16n8k16 {a0,a1,a2,a3}
// g_Kp: per kv-tile: [j 0..15][kkp 0..3][lane] -> {b0(2kkp),b1(2kkp),b0(2kkp+1),b1(2kkp+1)}, n=kv, k=E
// g_Vp: per kv-tile: [j 0..15][kkp 0..3][lane] -> same, n=E, k=kv
__device__ uint4 g_Qp[B_DIM * S_DIM * E_DIM / 8];
__device__ uint4 g_Kp[B_DIM * S_DIM * E_DIM / 8];
__device__ uint4 g_Vp[B_DIM * S_DIM * E_DIM / 8];

__device__ __forceinline__ uint32_t smem_to_u32(const void* p) {
    uint32_t a;
    asm("{ .reg .u64 t; cvta.to.shared.u64 t, %1; cvt.u32.u64 %0, t; }" : "=r"(a) : "l"(p));
    return a;
}

__device__ __forceinline__ void mma_f16(float* d, const uint32_t* a, const uint32_t* b) {
    asm volatile(
        "mma.sync.aligned.m16n8k16.row.col.f32.f16.f16.f32 "
        "{%0,%1,%2,%3}, {%4,%5,%6,%7}, {%8,%9}, {%0,%1,%2,%3};"
        : "+f"(d[0]), "+f"(d[1]), "+f"(d[2]), "+f"(d[3])
        : "r"(a[0]), "r"(a[1]), "r"(a[2]), "r"(a[3]), "r"(b[0]), "r"(b[1]));
}

__device__ __forceinline__ uint32_t pack_h2(float lo, float hi) {
    __half2 h = __floats2half2_rn(lo, hi);
    return *reinterpret_cast<uint32_t*>(&h);
}

__device__ __forceinline__ void cp_async16(uint32_t saddr, const void* g) {
    asm volatile("cp.async.cg.shared.global [%0], [%1], 16;" :: "r"(saddr), "l"(g));
}
#define CP_COMMIT() asm volatile("cp.async.commit_group;" ::: "memory")
#define CP_WAIT1()  asm volatile("cp.async.wait_group 1;" ::: "memory")

// ======================= projection (scalar fp32 core) =====================
// grid = ((B*S)/128, 3): which 0->Q (pre-scaled by log2e/sqrt(E)), 1->K, 2->V.
__global__ __launch_bounds__(256) void proj_kernel(
    const float* __restrict__ x,
    const float* __restrict__ Wq, const float* __restrict__ bq,
    const float* __restrict__ Wk, const float* __restrict__ bk,
    const float* __restrict__ Wv, const float* __restrict__ bvp)
{
    extern __shared__ float sm[];
    float* xs = sm;              // [e][s] 128x128
    float* ws = sm + 128 * 128;  // [e][o] 128x128

    const int t = threadIdx.x;
    const int which = blockIdx.y;
    const float* __restrict__ W  = (which == 0) ? Wq : (which == 1) ? Wk : Wv;
    const float* __restrict__ bb = (which == 0) ? bq : (which == 1) ? bk : bvp;
    const float scale = (which == 0) ? (0.08838834764831845f * 1.4426950408889634f) : 1.0f;

    const int row_base = blockIdx.x * 128;
    const int rm = t & 7, cm = t >> 3, c0 = 4 * cm;
    #pragma unroll
    for (int p = 0; p < 4; ++p) {
        const int r0 = 32 * p + 4 * rm;
        float4 v0 = *(const float4*)&x[(row_base + r0 + 0) * E_DIM + c0];
        float4 v1 = *(const float4*)&x[(row_base + r0 + 1) * E_DIM + c0];
        float4 v2 = *(const float4*)&x[(row_base + r0 + 2) * E_DIM + c0];
        float4 v3 = *(const float4*)&x[(row_base + r0 + 3) * E_DIM + c0];
        *(float4*)&xs[(c0 + 0) * 128 + r0] = make_float4(v0.x, v1.x, v2.x, v3.x);
        *(float4*)&xs[(c0 + 1) * 128 + r0] = make_float4(v0.y, v1.y, v2.y, v3.y);
        *(float4*)&xs[(c0 + 2) * 128 + r0] = make_float4(v0.z, v1.z, v2.z, v3.z);
        *(float4*)&xs[(c0 + 3) * 128 + r0] = make_float4(v0.w, v1.w, v2.w, v3.w);
        float4 u0 = *(const float4*)&W[(r0 + 0) * E_DIM + c0];
        float4 u1 = *(const float4*)&W[(r0 + 1) * E_DIM + c0];
        float4 u2 = *(const float4*)&W[(r0 + 2) * E_DIM + c0];
        float4 u3 = *(const float4*)&W[(r0 + 3) * E_DIM + c0];
        *(float4*)&ws[(c0 + 0) * 128 + r0] = make_float4(u0.x, u1.x, u2.x, u3.x);
        *(float4*)&ws[(c0 + 1) * 128 + r0] = make_float4(u0.y, u1.y, u2.y, u3.y);
        *(float4*)&ws[(c0 + 2) * 128 + r0] = make_float4(u0.z, u1.z, u2.z, u3.z);
        *(float4*)&ws[(c0 + 3) * 128 + r0] = make_float4(u0.w, u1.w, u2.w, u3.w);
    }
    __syncthreads();

    const int og = t >> 4, sg = t & 15;
    const int o0 = 8 * og, sA = 4 * sg, sB = 64 + 4 * sg;

    float acc[8][8];
    #pragma unroll
    for (int r = 0; r < 8; ++r)
        #pragma unroll
        for (int c = 0; c < 8; ++c) acc[r][c] = 0.0f;

    #pragma unroll 8
    for (int e = 0; e < 128; ++e) {
        float4 a0 = *(const float4*)&ws[e * 128 + o0];
        float4 a1 = *(const float4*)&ws[e * 128 + o0 + 4];
        float4 b0 = *(const float4*)&xs[e * 128 + sA];
        float4 b1 = *(const float4*)&xs[e * 128 + sB];
        float av[8] = {a0.x, a0.y, a0.z, a0.w, a1.x, a1.y, a1.z, a1.w};
        float bw[8] = {b0.x, b0.y, b0.z, b0.w, b1.x, b1.y, b1.z, b1.w};
        #pragma unroll
        for (int r = 0; r < 8; ++r)
            #pragma unroll
            for (int c = 0; c < 8; ++c) acc[r][c] += av[r] * bw[c];
    }

    #pragma unroll
    for (int r = 0; r < 8; ++r) {
        const float bv = __ldg(&bb[o0 + r]);
        #pragma unroll
        for (int c = 0; c < 8; ++c) acc[r][c] = (acc[r][c] + bv) * scale;
    }

    __syncthreads();
    float* nat = sm;
    #pragma unroll
    for (int r = 0; r < 8; ++r) {
        *(float4*)&nat[(o0 + r) * 132 + sA] = make_float4(acc[r][0], acc[r][1], acc[r][2], acc[r][3]);
        *(float4*)&nat[(o0 + r) * 132 + sB] = make_float4(acc[r][4], acc[r][5], acc[r][6], acc[r][7]);
    }
    __syncthreads();

    const int lane = t & 31, wid = t >> 5;
    const int rr = lane >> 2, cc = lane & 3;

    if (which == 0) {
        const size_t mbase = ((size_t)(row_base >> 4) + (size_t)wid) * 256;
        const int r0 = 16 * wid + rr;
        #pragma unroll
        for (int kk = 0; kk < 8; ++kk) {
            const int e0 = 16 * kk + 2 * cc;
            uint4 v;
            v.x = pack_h2(nat[e0 * 132 + r0],       nat[(e0 + 1) * 132 + r0]);
            v.y = pack_h2(nat[e0 * 132 + r0 + 8],   nat[(e0 + 1) * 132 + r0 + 8]);
            v.z = pack_h2(nat[(e0 + 8) * 132 + r0],     nat[(e0 + 9) * 132 + r0]);
            v.w = pack_h2(nat[(e0 + 8) * 132 + r0 + 8], nat[(e0 + 9) * 132 + r0 + 8]);
            g_Qp[mbase + (size_t)kk * 32 + lane] = v;
        }
    } else if (which == 1) {
        const int b = row_base / S_DIM, s_in = row_base % S_DIM, kt = s_in >> 7;
        const size_t tbase = (size_t)(b * 64 + kt) * 2048;
        #pragma unroll
        for (int jj = 0; jj < 2; ++jj) {
            const int j = 2 * wid + jj;
            const int srow = 8 * j + rr;
            #pragma unroll
            for (int kkp = 0; kkp < 4; ++kkp) {
                const int e0 = 32 * kkp + 2 * cc;
                const int e1 = e0 + 16;
                uint4 v;
                v.x = pack_h2(nat[e0 * 132 + srow],       nat[(e0 + 1) * 132 + srow]);
                v.y = pack_h2(nat[(e0 + 8) * 132 + srow], nat[(e0 + 9) * 132 + srow]);
                v.z = pack_h2(nat[e1 * 132 + srow],       nat[(e1 + 1) * 132 + srow]);
                v.w = pack_h2(nat[(e1 + 8) * 132 + srow], nat[(e1 + 9) * 132 + srow]);
                g_Kp[tbase + (size_t)j * 128 + kkp * 32 + lane] = v;
            }
        }
    } else {
        const int b = row_base / S_DIM, s_in = row_base % S_DIM, kt = s_in >> 7;
        const size_t tbase = (size_t)(b * 64 + kt) * 2048;
        #pragma unroll
        for (int jj = 0; jj < 2; ++jj) {
            const int j = 2 * wid + jj;
            const int erow = 8 * j + rr;
            #pragma unroll
            for (int kkp = 0; kkp < 4; ++kkp) {
                const int s0 = 32 * kkp + 2 * cc;
                const int s1 = s0 + 16;
                float2 p00 = *(const float2*)&nat[erow * 132 + s0];
                float2 p01 = *(const float2*)&nat[erow * 132 + s0 + 8];
                float2 p10 = *(const float2*)&nat[erow * 132 + s1];
                float2 p11 = *(const float2*)&nat[erow * 132 + s1 + 8];
                uint4 v;
                v.x = pack_h2(p00.x, p00.y);
                v.y = pack_h2(p01.x, p01.y);
                v.z = pack_h2(p10.x, p10.y);
                v.w = pack_h2(p11.x, p11.y);
                g_Vp[tbase + (size_t)j * 128 + kkp * 32 + lane] = v;
            }
        }
    }
}

// ================= fp16 flash attention: 4 fat warps ======================
// grid (S/128, B), 128 threads = 4 warps; warp w owns 32 q rows (m-tiles 2w,
// 2w+1) x all 128 kv. K-frag loads feed 4 MMAs -> SMEM traffic ~halved.
// SMEM uint4: buf0 K[0,2048) V[2048,4096); buf1 [4096,8192); Q [8192,10240).
__device__ __forceinline__ void prefetch_tile(uint32_t sdst, const uint4* ksrc,
                                              const uint4* vsrc, int t) {
    #pragma unroll
    for (int i = 0; i < 16; ++i) {
        const int s = t + i * 128;
        cp_async16(sdst + s * 16, ksrc + s);
        cp_async16(sdst + 32768 + s * 16, vsrc + s);
    }
}

__global__ __launch_bounds__(128, 1) void attn_mma_kernel(float* __restrict__ out)
{
    extern __shared__ uint4 sbuf[];
    const int t = threadIdx.x;
    const int lane = t & 31, w = t >> 5;
    const int rr = lane >> 2, cc = lane & 3;
    const int b = blockIdx.y, q0 = blockIdx.x * 128;
    const uint32_t sb = smem_to_u32(sbuf);

    // ---- Q fragments into SMEM (one-time) ----
    uint4* Qs = sbuf + 8192;
    {
        const uint4* qsrc = &g_Qp[((size_t)(b * S_DIM + q0) >> 4) * 256];
        #pragma unroll
        for (int i = 0; i < 16; ++i) Qs[t + i * 128] = qsrc[t + i * 128];
    }

    float oacc[2][16][4];
    #pragma unroll
    for (int m = 0; m < 2; ++m)
        #pragma unroll
        for (int j = 0; j < 16; ++j)
            #pragma unroll
            for (int q = 0; q < 4; ++q) oacc[m][j][q] = 0.0f;
    float rsum[2][2] = {{0.0f, 0.0f}, {0.0f, 0.0f}};

    const uint4* kbase = &g_Kp[(size_t)(b * 64) * 2048];
    const uint4* vbase = &g_Vp[(size_t)(b * 64) * 2048];

    prefetch_tile(sb, kbase, vbase, t);
    CP_COMMIT();

    const int mt0 = 2 * w * 256;     // warp's m-tile bases in Qs (uint4 idx)
    const int mt1 = mt0 + 256;

    for (int kt = 0; kt < 64; ++kt) {
        __syncthreads();   // prior compute done: next buffer free
        const int nkt = (kt + 1) & 63;
        prefetch_tile(sb + ((kt + 1) & 1) * 65536,
                      kbase + (size_t)nkt * 2048, vbase + (size_t)nkt * 2048, t);
        CP_COMMIT();
        CP_WAIT1();
        __syncthreads();   // tile kt visible to all (also covers Q copy at kt=0)

        const uint4* Ks = sbuf + (kt & 1) * 4096;
        const uint4* Vs = Ks + 2048;

        #pragma unroll
        for (int h = 0; h < 2; ++h) {     // kv half: cols 64h .. 64h+63
            // ---- QK: scores for both m-tiles, this half's 8 j-tiles ----
            float f[2][8][4];
            #pragma unroll
            for (int m = 0; m < 2; ++m)
                #pragma unroll
                for (int jj = 0; jj < 8; ++jj)
                    #pragma unroll
                    for (int q = 0; q < 4; ++q) f[m][jj][q] = 0.0f;

            #pragma unroll
            for (int kkp = 0; kkp < 4; ++kkp) {
                uint4 q0a = Qs[mt0 + (2 * kkp) * 32 + lane];
                uint4 q0b = Qs[mt0 + (2 * kkp + 1) * 32 + lane];
                uint4 q1a = Qs[mt1 + (2 * kkp) * 32 + lane];
                uint4 q1b = Qs[mt1 + (2 * kkp + 1) * 32 + lane];
                uint32_t a0a[4] = {q0a.x, q0a.y, q0a.z, q0a.w};
                uint32_t a0b[4] = {q0b.x, q0b.y, q0b.z, q0b.w};
                uint32_t a1a[4] = {q1a.x, q1a.y, q1a.z, q1a.w};
                uint32_t a1b[4] = {q1b.x, q1b.y, q1b.z, q1b.w};
                #pragma unroll
                for (int jj = 0; jj < 8; ++jj) {
                    uint4 bv = Ks[(8 * h + jj) * 128 + kkp * 32 + lane];
                    uint32_t b0[2] = {bv.x, bv.y}, b1[2] = {bv.z, bv.w};
                    mma_f16(f[0][jj], a0a, b0);
                    mma_f16(f[0][jj], a0b, b1);
                    mma_f16(f[1][jj], a1a, b0);
                    mma_f16(f[1][jj], a1b, b1);
                }
            }

            // ---- P = exp2(S) in registers ----
            uint32_t ph[2][8][2];
            #pragma unroll
            for (int m = 0; m < 2; ++m)
                #pragma unroll
                for (int jj = 0; jj < 8; ++jj) {
                    __half2 h01 = __floats2half2_rn(exp2f(f[m][jj][0]), exp2f(f[m][jj][1]));
                    __half2 h23 = __floats2half2_rn(exp2f(f[m][jj][2]), exp2f(f[m][jj][3]));
                    float2 p01 = __half22float2(h01);   // denominator uses the
                    float2 p23 = __half22float2(h23);   // SAME rounded values
                    rsum[m][0] += p01.x + p01.y;
                    rsum[m][1] += p23.x + p23.y;
                    ph[m][jj][0] = *reinterpret_cast<uint32_t*>(&h01);
                    ph[m][jj][1] = *reinterpret_cast<uint32_t*>(&h23);
                }

            // ---- O += P_half V_half (k = kv rows 64h..64h+63 -> kkp 2h,2h+1) ----
            #pragma unroll
            for (int p = 0; p < 2; ++p) {
                uint32_t a0m0[4] = {ph[0][4*p][0],   ph[0][4*p][1],   ph[0][4*p+1][0], ph[0][4*p+1][1]};
                uint32_t a1m0[4] = {ph[0][4*p+2][0], ph[0][4*p+2][1], ph[0][4*p+3][0], ph[0][4*p+3][1]};
                uint32_t a0m1[4] = {ph[1][4*p][0],   ph[1][4*p][1],   ph[1][4*p+1][0], ph[1][4*p+1][1]};
                uint32_t a1m1[4] = {ph[1][4*p+2][0], ph[1][4*p+2][1], ph[1][4*p+3][0], ph[1][4*p+3][1]};
                #pragma unroll
                for (int j = 0; j < 16; ++j) {
                    uint4 bv = Vs[j * 128 + (2 * h + p) * 32 + lane];
                    uint32_t b0[2] = {bv.x, bv.y}, b1[2] = {bv.z, bv.w};
                    mma_f16(oacc[0][j], a0m0, b0);
                    mma_f16(oacc[0][j], a1m0, b1);
                    mma_f16(oacc[1][j], a0m1, b0);
                    mma_f16(oacc[1][j], a1m1, b1);
                }
            }
        }
    }

    // ---- row sums (quad xor-reduce) ----
    #pragma unroll
    for (int m = 0; m < 2; ++m)
        #pragma unroll
        for (int s = 0; s < 2; ++s) {
            float v = rsum[m][s];
            v += __shfl_xor_sync(0xffffffffu, v, 1);
            v += __shfl_xor_sync(0xffffffffu, v, 2);
            rsum[m][s] = v;
        }

    // ---- normalize + store ----
    #pragma unroll
    for (int m = 0; m < 2; ++m) {
        const size_t row0 = (size_t)b * S_DIM + q0 + 16 * (2 * w + m) + rr;
        const float inv0 = 1.0f / rsum[m][0];
        const float inv1 = 1.0f / rsum[m][1];
        #pragma unroll
        for (int j = 0; j < 16; ++j) {
            const int e = 8 * j + 2 * cc;
            *(float2*)&out[row0 * E_DIM + e] =
                make_float2(oacc[m][j][0] * inv0, oacc[m][j][1] * inv0);
            *(float2*)&out[(row0 + 8) * E_DIM + e] =
                make_float2(oacc[m][j][2] * inv1, oacc[m][j][3] * inv1);
        }
    }
}

// ============================== launch =====================================
extern "C" void kernel_launch(void* const* d_in, const int* in_sizes, int n_in,
                              void* d_out, int out_size)
{
    (void)in_sizes; (void)n_in; (void)out_size;
    const float* x  = (const float*)d_in[0];
    const float* Wq = (const float*)d_in[1];
    const float* bq = (const float*)d_in[2];
    const float* Wk = (const float*)d_in[3];
    const float* bk = (const float*)d_in[4];
    const float* Wv = (const float*)d_in[5];
    const float* bv = (const float*)d_in[6];
    float* out = (float*)d_out;

    cudaFuncSetAttribute(proj_kernel, cudaFuncAttributeMaxDynamicSharedMemorySize, 131072);
    cudaFuncSetAttribute(attn_mma_kernel, cudaFuncAttributeMaxDynamicSharedMemorySize, 163840);

    dim3 pg((B_DIM * S_DIM) / 128, 3);
    proj_kernel<<<pg, 256, 131072>>>(x, Wq, bq, Wk, bk, Wv, bv);

    dim3 ag(S_DIM / 128, B_DIM);
    attn_mma_kernel<<<ag, 128, 163840>>>(out);
}

// round 8
// speedup vs baseline: 1.0869x; 1.0869x over previous
#include <cuda_runtime.h>
#include <cuda_fp16.h>
#include <math.h>
#include <stdint.h>

#define B_DIM 2
#define S_DIM 8192
#define E_DIM 128

// fp16 fragment-permuted scratch (uint4 = 8 halves):
// g_Qp: per m-tile (16 q rows): [kk 0..7][lane] -> A-frag m16n8k16 {a0,a1,a2,a3}
// g_Kp: per kv-tile: [j 0..15][kkp 0..3][lane] -> {b0(2kkp),b1(2kkp),b0(2kkp+1),b1(2kkp+1)}
// g_Vp: per kv-tile: [j(e) 0..15][kkp(kv) 0..3][lane] -> same
__device__ uint4 g_Qp[B_DIM * S_DIM * E_DIM / 8];
__device__ uint4 g_Kp[B_DIM * S_DIM * E_DIM / 8];
__device__ uint4 g_Vp[B_DIM * S_DIM * E_DIM / 8];

__device__ __forceinline__ uint32_t smem_to_u32(const void* p) {
    uint32_t a;
    asm("{ .reg .u64 t; cvta.to.shared.u64 t, %1; cvt.u32.u64 %0, t; }" : "=r"(a) : "l"(p));
    return a;
}
__device__ __forceinline__ void mma_f16(float* d, const uint32_t* a, const uint32_t* b) {
    asm volatile(
        "mma.sync.aligned.m16n8k16.row.col.f32.f16.f16.f32 "
        "{%0,%1,%2,%3}, {%4,%5,%6,%7}, {%8,%9}, {%0,%1,%2,%3};"
        : "+f"(d[0]), "+f"(d[1]), "+f"(d[2]), "+f"(d[3])
        : "r"(a[0]), "r"(a[1]), "r"(a[2]), "r"(a[3]), "r"(b[0]), "r"(b[1]));
}
__device__ __forceinline__ uint32_t pack_h2(float lo, float hi) {
    __half2 h = __floats2half2_rn(lo, hi);
    return *reinterpret_cast<uint32_t*>(&h);
}
__device__ __forceinline__ float ex2f(float x) {
    float y; asm("ex2.approx.f32 %0, %1;" : "=f"(y) : "f"(x)); return y;
}
__device__ __forceinline__ void cp_async16(uint32_t saddr, const void* g) {
    asm volatile("cp.async.cg.shared.global [%0], [%1], 16;" :: "r"(saddr), "l"(g));
}
#define CP_COMMIT() asm volatile("cp.async.commit_group;" ::: "memory")
#define CP_WAIT1()  asm volatile("cp.async.wait_group 1;" ::: "memory")
#define CP_WAIT0()  asm volatile("cp.async.wait_group 0;" ::: "memory")

// ======================= projection (unchanged, works) =====================
__global__ __launch_bounds__(256) void proj_kernel(
    const float* __restrict__ x,
    const float* __restrict__ Wq, const float* __restrict__ bq,
    const float* __restrict__ Wk, const float* __restrict__ bk,
    const float* __restrict__ Wv, const float* __restrict__ bvp)
{
    extern __shared__ float sm[];
    float* xs = sm;
    float* ws = sm + 128 * 128;

    const int t = threadIdx.x;
    const int which = blockIdx.y;
    const float* __restrict__ W  = (which == 0) ? Wq : (which == 1) ? Wk : Wv;
    const float* __restrict__ bb = (which == 0) ? bq : (which == 1) ? bk : bvp;
    const float scale = (which == 0) ? (0.08838834764831845f * 1.4426950408889634f) : 1.0f;

    const int row_base = blockIdx.x * 128;
    const int rm = t & 7, cm = t >> 3, c0 = 4 * cm;
    #pragma unroll
    for (int p = 0; p < 4; ++p) {
        const int r0 = 32 * p + 4 * rm;
        float4 v0 = *(const float4*)&x[(row_base + r0 + 0) * E_DIM + c0];
        float4 v1 = *(const float4*)&x[(row_base + r0 + 1) * E_DIM + c0];
        float4 v2 = *(const float4*)&x[(row_base + r0 + 2) * E_DIM + c0];
        float4 v3 = *(const float4*)&x[(row_base + r0 + 3) * E_DIM + c0];
        *(float4*)&xs[(c0 + 0) * 128 + r0] = make_float4(v0.x, v1.x, v2.x, v3.x);
        *(float4*)&xs[(c0 + 1) * 128 + r0] = make_float4(v0.y, v1.y, v2.y, v3.y);
        *(float4*)&xs[(c0 + 2) * 128 + r0] = make_float4(v0.z, v1.z, v2.z, v3.z);
        *(float4*)&xs[(c0 + 3) * 128 + r0] = make_float4(v0.w, v1.w, v2.w, v3.w);
        float4 u0 = *(const float4*)&W[(r0 + 0) * E_DIM + c0];
        float4 u1 = *(const float4*)&W[(r0 + 1) * E_DIM + c0];
        float4 u2 = *(const float4*)&W[(r0 + 2) * E_DIM + c0];
        float4 u3 = *(const float4*)&W[(r0 + 3) * E_DIM + c0];
        *(float4*)&ws[(c0 + 0) * 128 + r0] = make_float4(u0.x, u1.x, u2.x, u3.x);
        *(float4*)&ws[(c0 + 1) * 128 + r0] = make_float4(u0.y, u1.y, u2.y, u3.y);
        *(float4*)&ws[(c0 + 2) * 128 + r0] = make_float4(u0.z, u1.z, u2.z, u3.z);
        *(float4*)&ws[(c0 + 3) * 128 + r0] = make_float4(u0.w, u1.w, u2.w, u3.w);
    }
    __syncthreads();

    const int og = t >> 4, sg = t & 15;
    const int o0 = 8 * og, sA = 4 * sg, sB = 64 + 4 * sg;

    float acc[8][8];
    #pragma unroll
    for (int r = 0; r < 8; ++r)
        #pragma unroll
        for (int c = 0; c < 8; ++c) acc[r][c] = 0.0f;

    #pragma unroll 8
    for (int e = 0; e < 128; ++e) {
        float4 a0 = *(const float4*)&ws[e * 128 + o0];
        float4 a1 = *(const float4*)&ws[e * 128 + o0 + 4];
        float4 b0 = *(const float4*)&xs[e * 128 + sA];
        float4 b1 = *(const float4*)&xs[e * 128 + sB];
        float av[8] = {a0.x, a0.y, a0.z, a0.w, a1.x, a1.y, a1.z, a1.w};
        float bw[8] = {b0.x, b0.y, b0.z, b0.w, b1.x, b1.y, b1.z, b1.w};
        #pragma unroll
        for (int r = 0; r < 8; ++r)
            #pragma unroll
            for (int c = 0; c < 8; ++c) acc[r][c] += av[r] * bw[c];
    }

    #pragma unroll
    for (int r = 0; r < 8; ++r) {
        const float bv = __ldg(&bb[o0 + r]);
        #pragma unroll
        for (int c = 0; c < 8; ++c) acc[r][c] = (acc[r][c] + bv) * scale;
    }

    __syncthreads();
    float* nat = sm;
    #pragma unroll
    for (int r = 0; r < 8; ++r) {
        *(float4*)&nat[(o0 + r) * 132 + sA] = make_float4(acc[r][0], acc[r][1], acc[r][2], acc[r][3]);
        *(float4*)&nat[(o0 + r) * 132 + sB] = make_float4(acc[r][4], acc[r][5], acc[r][6], acc[r][7]);
    }
    __syncthreads();

    const int lane = t & 31, wid = t >> 5;
    const int rr = lane >> 2, cc = lane & 3;

    if (which == 0) {
        const size_t mbase = ((size_t)(row_base >> 4) + (size_t)wid) * 256;
        const int r0 = 16 * wid + rr;
        #pragma unroll
        for (int kk = 0; kk < 8; ++kk) {
            const int e0 = 16 * kk + 2 * cc;
            uint4 v;
            v.x = pack_h2(nat[e0 * 132 + r0],       nat[(e0 + 1) * 132 + r0]);
            v.y = pack_h2(nat[e0 * 132 + r0 + 8],   nat[(e0 + 1) * 132 + r0 + 8]);
            v.z = pack_h2(nat[(e0 + 8) * 132 + r0],     nat[(e0 + 9) * 132 + r0]);
            v.w = pack_h2(nat[(e0 + 8) * 132 + r0 + 8], nat[(e0 + 9) * 132 + r0 + 8]);
            g_Qp[mbase + (size_t)kk * 32 + lane] = v;
        }
    } else if (which == 1) {
        const int b = row_base / S_DIM, s_in = row_base % S_DIM, kt = s_in >> 7;
        const size_t tbase = (size_t)(b * 64 + kt) * 2048;
        #pragma unroll
        for (int jj = 0; jj < 2; ++jj) {
            const int j = 2 * wid + jj;
            const int srow = 8 * j + rr;
            #pragma unroll
            for (int kkp = 0; kkp < 4; ++kkp) {
                const int e0 = 32 * kkp + 2 * cc;
                const int e1 = e0 + 16;
                uint4 v;
                v.x = pack_h2(nat[e0 * 132 + srow],       nat[(e0 + 1) * 132 + srow]);
                v.y = pack_h2(nat[(e0 + 8) * 132 + srow], nat[(e0 + 9) * 132 + srow]);
                v.z = pack_h2(nat[e1 * 132 + srow],       nat[(e1 + 1) * 132 + srow]);
                v.w = pack_h2(nat[(e1 + 8) * 132 + srow], nat[(e1 + 9) * 132 + srow]);
                g_Kp[tbase + (size_t)j * 128 + kkp * 32 + lane] = v;
            }
        }
    } else {
        const int b = row_base / S_DIM, s_in = row_base % S_DIM, kt = s_in >> 7;
        const size_t tbase = (size_t)(b * 64 + kt) * 2048;
        #pragma unroll
        for (int jj = 0; jj < 2; ++jj) {
            const int j = 2 * wid + jj;
            const int erow = 8 * j + rr;
            #pragma unroll
            for (int kkp = 0; kkp < 4; ++kkp) {
                const int s0 = 32 * kkp + 2 * cc;
                const int s1 = s0 + 16;
                float2 p00 = *(const float2*)&nat[erow * 132 + s0];
                float2 p01 = *(const float2*)&nat[erow * 132 + s0 + 8];
                float2 p10 = *(const float2*)&nat[erow * 132 + s1];
                float2 p11 = *(const float2*)&nat[erow * 132 + s1 + 8];
                uint4 v;
                v.x = pack_h2(p00.x, p00.y);
                v.y = pack_h2(p01.x, p01.y);
                v.z = pack_h2(p10.x, p10.y);
                v.w = pack_h2(p11.x, p11.y);
                g_Vp[tbase + (size_t)j * 128 + kkp * 32 + lane] = v;
            }
        }
    }
}

// ========== ping-pong fp16 flash attention: 4 QK warps + 4 PV warps ========
// grid (S/128, B), 256 threads. QK warp g: rows 32g, all kv; writes P(s).
// PV warp g: rows 32g, all e; consumes P(s-1). P via SMEM in A-frag layout.
// SMEM uint4: Kb[2][2048] Vb[2][2048]@4096 Pb[2][2048]@8192 Qs[2048]@12288,
// rs floats @14336.
__global__ __launch_bounds__(256, 1) void attn_mma_kernel(float* __restrict__ out)
{
    extern __shared__ uint4 sb4[];
    uint4* Kb = sb4;
    uint4* Vb = sb4 + 4096;
    uint4* Pb = sb4 + 8192;
    uint4* Qs = sb4 + 12288;
    float* rs = (float*)(sb4 + 14336);

    const int t = threadIdx.x;
    const int lane = t & 31, wid = t >> 5;
    const int rr = lane >> 2, cc = lane & 3;
    const int g = wid & 3;
    const bool isQK = wid < 4;
    const int b = blockIdx.y, q0 = blockIdx.x * 128;
    const uint32_t sb = smem_to_u32(sb4);

    // Q fragments -> SMEM (one-time; visible after step-0 barriers)
    {
        const uint4* qsrc = &g_Qp[((size_t)(b * S_DIM + q0) >> 4) * 256];
        #pragma unroll
        for (int i = 0; i < 8; ++i) Qs[t + i * 256] = qsrc[t + i * 256];
    }

    float oacc[2][16][4];
    #pragma unroll
    for (int m = 0; m < 2; ++m)
        #pragma unroll
        for (int j = 0; j < 16; ++j)
            #pragma unroll
            for (int q = 0; q < 4; ++q) oacc[m][j][q] = 0.0f;
    float rsum[2][2] = {{0.0f, 0.0f}, {0.0f, 0.0f}};

    const uint4* kbase = &g_Kp[(size_t)(b * 64) * 2048];
    const uint4* vbase = &g_Vp[(size_t)(b * 64) * 2048];

    // prologue: K(0) -> Kb[0]
    #pragma unroll
    for (int i = 0; i < 8; ++i)
        cp_async16(sb + (t + i * 256) * 16, kbase + t + i * 256);
    CP_COMMIT();

    const int mt0 = 2 * g, mt1 = 2 * g + 1;

    for (int s = 0; s <= 64; ++s) {
        __syncthreads();   // compute(s-1) done before buffer overwrite
        if (s < 64) {
            if (s < 63) {  // K(s+1) -> Kb[(s+1)&1]
                const uint4* ks = kbase + (size_t)(s + 1) * 2048;
                const uint32_t kd = sb + (((s + 1) & 1) * 2048) * 16;
                #pragma unroll
                for (int i = 0; i < 8; ++i)
                    cp_async16(kd + (t + i * 256) * 16, ks + t + i * 256);
            }
            {              // V(s) -> Vb[s&1]
                const uint4* vs = vbase + (size_t)s * 2048;
                const uint32_t vd = sb + (4096 + (s & 1) * 2048) * 16;
                #pragma unroll
                for (int i = 0; i < 8; ++i)
                    cp_async16(vd + (t + i * 256) * 16, vs + t + i * 256);
            }
            CP_COMMIT();
            CP_WAIT1();
        } else {
            CP_WAIT0();
        }
        __syncthreads();

        if (isQK) {
            if (s < 64) {
                const uint4* Kt = Kb + (s & 1) * 2048;
                uint4* Pt = Pb + (s & 1) * 2048;
                #pragma unroll
                for (int h = 0; h < 2; ++h) {
                    float f[2][8][4];
                    #pragma unroll
                    for (int m = 0; m < 2; ++m)
                        #pragma unroll
                        for (int jl = 0; jl < 8; ++jl)
                            #pragma unroll
                            for (int q = 0; q < 4; ++q) f[m][jl][q] = 0.0f;

                    #pragma unroll
                    for (int kkp = 0; kkp < 4; ++kkp) {
                        uint4 q00 = Qs[(mt0 * 8 + 2 * kkp) * 32 + lane];
                        uint4 q01 = Qs[(mt0 * 8 + 2 * kkp + 1) * 32 + lane];
                        uint4 q10 = Qs[(mt1 * 8 + 2 * kkp) * 32 + lane];
                        uint4 q11 = Qs[(mt1 * 8 + 2 * kkp + 1) * 32 + lane];
                        uint32_t a00[4] = {q00.x, q00.y, q00.z, q00.w};
                        uint32_t a01[4] = {q01.x, q01.y, q01.z, q01.w};
                        uint32_t a10[4] = {q10.x, q10.y, q10.z, q10.w};
                        uint32_t a11[4] = {q11.x, q11.y, q11.z, q11.w};
                        #pragma unroll
                        for (int jl = 0; jl < 8; ++jl) {
                            uint4 bv = Kt[((8 * h + jl) * 4 + kkp) * 32 + lane];
                            uint32_t b0[2] = {bv.x, bv.y}, b1[2] = {bv.z, bv.w};
                            mma_f16(f[0][jl], a00, b0);
                            mma_f16(f[0][jl], a01, b1);
                            mma_f16(f[1][jl], a10, b0);
                            mma_f16(f[1][jl], a11, b1);
                        }
                    }

                    // exp2 -> fp16 P (A-frag-direct STS.128), rsum on rounded values
                    #pragma unroll
                    for (int m = 0; m < 2; ++m)
                        #pragma unroll
                        for (int pr = 0; pr < 4; ++pr) {
                            __half2 hx = __floats2half2_rn(ex2f(f[m][2*pr][0]),   ex2f(f[m][2*pr][1]));
                            __half2 hy = __floats2half2_rn(ex2f(f[m][2*pr][2]),   ex2f(f[m][2*pr][3]));
                            __half2 hz = __floats2half2_rn(ex2f(f[m][2*pr+1][0]), ex2f(f[m][2*pr+1][1]));
                            __half2 hw = __floats2half2_rn(ex2f(f[m][2*pr+1][2]), ex2f(f[m][2*pr+1][3]));
                            float2 px = __half22float2(hx), py = __half22float2(hy);
                            float2 pz = __half22float2(hz), pw = __half22float2(hw);
                            rsum[m][0] += (px.x + px.y) + (pz.x + pz.y);
                            rsum[m][1] += (py.x + py.y) + (pw.x + pw.y);
                            uint4 v;
                            v.x = *reinterpret_cast<uint32_t*>(&hx);
                            v.y = *reinterpret_cast<uint32_t*>(&hy);
                            v.z = *reinterpret_cast<uint32_t*>(&hz);
                            v.w = *reinterpret_cast<uint32_t*>(&hw);
                            Pt[((2 * g + m) * 8 + 4 * h + pr) * 32 + lane] = v;
                        }
                }
            }
        } else {
            if (s >= 1) {
                const int u = s - 1;
                const uint4* Vt = Vb + (u & 1) * 2048;
                const uint4* Pt = Pb + (u & 1) * 2048;
                #pragma unroll
                for (int kkp = 0; kkp < 4; ++kkp) {
                    uint4 A00 = Pt[(mt0 * 8 + 2 * kkp) * 32 + lane];
                    uint4 A01 = Pt[(mt0 * 8 + 2 * kkp + 1) * 32 + lane];
                    uint4 A10 = Pt[(mt1 * 8 + 2 * kkp) * 32 + lane];
                    uint4 A11 = Pt[(mt1 * 8 + 2 * kkp + 1) * 32 + lane];
                    uint32_t a00[4] = {A00.x, A00.y, A00.z, A00.w};
                    uint32_t a01[4] = {A01.x, A01.y, A01.z, A01.w};
                    uint32_t a10[4] = {A10.x, A10.y, A10.z, A10.w};
                    uint32_t a11[4] = {A11.x, A11.y, A11.z, A11.w};
                    #pragma unroll
                    for (int j = 0; j < 16; ++j) {
                        uint4 bv = Vt[(j * 4 + kkp) * 32 + lane];
                        uint32_t b0[2] = {bv.x, bv.y}, b1[2] = {bv.z, bv.w};
                        mma_f16(oacc[0][j], a00, b0);
                        mma_f16(oacc[0][j], a01, b1);
                        mma_f16(oacc[1][j], a10, b0);
                        mma_f16(oacc[1][j], a11, b1);
                    }
                }
            }
        }
    }

    // ---- rsum handoff QK -> PV ----
    if (isQK) {
        #pragma unroll
        for (int m = 0; m < 2; ++m)
            #pragma unroll
            for (int hh = 0; hh < 2; ++hh) {
                float v = rsum[m][hh];
                v += __shfl_xor_sync(0xffffffffu, v, 1);
                v += __shfl_xor_sync(0xffffffffu, v, 2);
                rsum[m][hh] = v;
            }
        if (cc == 0) {
            #pragma unroll
            for (int m = 0; m < 2; ++m) {
                rs[16 * (2 * g + m) + rr]     = rsum[m][0];
                rs[16 * (2 * g + m) + rr + 8] = rsum[m][1];
            }
        }
    }
    __syncthreads();

    if (!isQK) {
        #pragma unroll
        for (int m = 0; m < 2; ++m) {
            const int rl0 = 16 * (2 * g + m) + rr;
            const float inv0 = 1.0f / rs[rl0];
            const float inv1 = 1.0f / rs[rl0 + 8];
            const size_t row0 = (size_t)b * S_DIM + q0 + rl0;
            #pragma unroll
            for (int j = 0; j < 16; ++j) {
                const int e = 8 * j + 2 * cc;
                *(float2*)&out[row0 * E_DIM + e] =
                    make_float2(oacc[m][j][0] * inv0, oacc[m][j][1] * inv0);
                *(float2*)&out[(row0 + 8) * E_DIM + e] =
                    make_float2(oacc[m][j][2] * inv1, oacc[m][j][3] * inv1);
            }
        }
    }
}

// ============================== launch =====================================
extern "C" void kernel_launch(void* const* d_in, const int* in_sizes, int n_in,
                              void* d_out, int out_size)
{
    (void)in_sizes; (void)n_in; (void)out_size;
    const float* x  = (const float*)d_in[0];
    const float* Wq = (const float*)d_in[1];
    const float* bq = (const float*)d_in[2];
    const float* Wk = (const float*)d_in[3];
    const float* bk = (const float*)d_in[4];
    const float* Wv = (const float*)d_in[5];
    const float* bv = (const float*)d_in[6];
    float* out = (float*)d_out;

    const int attn_smem = 14336 * 16 + 512;   // 229888 B

    cudaFuncSetAttribute(proj_kernel, cudaFuncAttributeMaxDynamicSharedMemorySize, 131072);
    cudaFuncSetAttribute(attn_mma_kernel, cudaFuncAttributeMaxDynamicSharedMemorySize, attn_smem);

    dim3 pg((B_DIM * S_DIM) / 128, 3);
    proj_kernel<<<pg, 256, 131072>>>(x, Wq, bq, Wk, bk, Wv, bv);

    dim3 ag(S_DIM / 128, B_DIM);
    attn_mma_kernel<<<ag, 256, attn_smem>>>(out);
}

// round 9
// speedup vs baseline: 1.1971x; 1.1013x over previous
#include <cuda_runtime.h>
#include <cuda_fp16.h>
#include <math.h>
#include <stdint.h>

#define B_DIM 2
#define S_DIM 8192
#define E_DIM 128

// fp16 fragment-permuted scratch (uint4 = 8 halves):
// g_Qp: per m-tile (16 q rows): [kk 0..7][lane] -> A-frag m16n8k16 {a0,a1,a2,a3}
// g_Kp: per kv-tile: [j 0..15][kkp 0..3][lane] -> {b0(2kkp),b1(2kkp),b0(2kkp+1),b1(2kkp+1)} (n=kv j, k=E)
// g_Vp: per kv-tile: [j(e) 0..15][kkp(kv) 0..3][lane] -> same (n=E j, k=kv)
__device__ uint4 g_Qp[B_DIM * S_DIM * E_DIM / 8];
__device__ uint4 g_Kp[B_DIM * S_DIM * E_DIM / 8];
__device__ uint4 g_Vp[B_DIM * S_DIM * E_DIM / 8];

__device__ __forceinline__ uint32_t smem_to_u32(const void* p) {
    uint32_t a;
    asm("{ .reg .u64 t; cvta.to.shared.u64 t, %1; cvt.u32.u64 %0, t; }" : "=r"(a) : "l"(p));
    return a;
}
__device__ __forceinline__ void mma_f16(float* d, const uint32_t* a, const uint32_t* b) {
    asm volatile(
        "mma.sync.aligned.m16n8k16.row.col.f32.f16.f16.f32 "
        "{%0,%1,%2,%3}, {%4,%5,%6,%7}, {%8,%9}, {%0,%1,%2,%3};"
        : "+f"(d[0]), "+f"(d[1]), "+f"(d[2]), "+f"(d[3])
        : "r"(a[0]), "r"(a[1]), "r"(a[2]), "r"(a[3]), "r"(b[0]), "r"(b[1]));
}
__device__ __forceinline__ uint32_t pack_h2(float lo, float hi) {
    __half2 h = __floats2half2_rn(lo, hi);
    return *reinterpret_cast<uint32_t*>(&h);
}
__device__ __forceinline__ float ex2f(float x) {
    float y; asm("ex2.approx.f32 %0, %1;" : "=f"(y) : "f"(x)); return y;
}
__device__ __forceinline__ void cp_async16(uint32_t saddr, const void* g) {
    asm volatile("cp.async.cg.shared.global [%0], [%1], 16;" :: "r"(saddr), "l"(g));
}
#define CP_COMMIT() asm volatile("cp.async.commit_group;" ::: "memory")
#define CP_WAIT1()  asm volatile("cp.async.wait_group 1;" ::: "memory")

// ======================= projection (unchanged, works) =====================
__global__ __launch_bounds__(256) void proj_kernel(
    const float* __restrict__ x,
    const float* __restrict__ Wq, const float* __restrict__ bq,
    const float* __restrict__ Wk, const float* __restrict__ bk,
    const float* __restrict__ Wv, const float* __restrict__ bvp)
{
    extern __shared__ float sm[];
    float* xs = sm;
    float* ws = sm + 128 * 128;

    const int t = threadIdx.x;
    const int which = blockIdx.y;
    const float* __restrict__ W  = (which == 0) ? Wq : (which == 1) ? Wk : Wv;
    const float* __restrict__ bb = (which == 0) ? bq : (which == 1) ? bk : bvp;
    const float scale = (which == 0) ? (0.08838834764831845f * 1.4426950408889634f) : 1.0f;

    const int row_base = blockIdx.x * 128;
    const int rm = t & 7, cm = t >> 3, c0 = 4 * cm;
    #pragma unroll
    for (int p = 0; p < 4; ++p) {
        const int r0 = 32 * p + 4 * rm;
        float4 v0 = *(const float4*)&x[(row_base + r0 + 0) * E_DIM + c0];
        float4 v1 = *(const float4*)&x[(row_base + r0 + 1) * E_DIM + c0];
        float4 v2 = *(const float4*)&x[(row_base + r0 + 2) * E_DIM + c0];
        float4 v3 = *(const float4*)&x[(row_base + r0 + 3) * E_DIM + c0];
        *(float4*)&xs[(c0 + 0) * 128 + r0] = make_float4(v0.x, v1.x, v2.x, v3.x);
        *(float4*)&xs[(c0 + 1) * 128 + r0] = make_float4(v0.y, v1.y, v2.y, v3.y);
        *(float4*)&xs[(c0 + 2) * 128 + r0] = make_float4(v0.z, v1.z, v2.z, v3.z);
        *(float4*)&xs[(c0 + 3) * 128 + r0] = make_float4(v0.w, v1.w, v2.w, v3.w);
        float4 u0 = *(const float4*)&W[(r0 + 0) * E_DIM + c0];
        float4 u1 = *(const float4*)&W[(r0 + 1) * E_DIM + c0];
        float4 u2 = *(const float4*)&W[(r0 + 2) * E_DIM + c0];
        float4 u3 = *(const float4*)&W[(r0 + 3) * E_DIM + c0];
        *(float4*)&ws[(c0 + 0) * 128 + r0] = make_float4(u0.x, u1.x, u2.x, u3.x);
        *(float4*)&ws[(c0 + 1) * 128 + r0] = make_float4(u0.y, u1.y, u2.y, u3.y);
        *(float4*)&ws[(c0 + 2) * 128 + r0] = make_float4(u0.z, u1.z, u2.z, u3.z);
        *(float4*)&ws[(c0 + 3) * 128 + r0] = make_float4(u0.w, u1.w, u2.w, u3.w);
    }
    __syncthreads();

    const int og = t >> 4, sg = t & 15;
    const int o0 = 8 * og, sA = 4 * sg, sB = 64 + 4 * sg;

    float acc[8][8];
    #pragma unroll
    for (int r = 0; r < 8; ++r)
        #pragma unroll
        for (int c = 0; c < 8; ++c) acc[r][c] = 0.0f;

    #pragma unroll 8
    for (int e = 0; e < 128; ++e) {
        float4 a0 = *(const float4*)&ws[e * 128 + o0];
        float4 a1 = *(const float4*)&ws[e * 128 + o0 + 4];
        float4 b0 = *(const float4*)&xs[e * 128 + sA];
        float4 b1 = *(const float4*)&xs[e * 128 + sB];
        float av[8] = {a0.x, a0.y, a0.z, a0.w, a1.x, a1.y, a1.z, a1.w};
        float bw[8] = {b0.x, b0.y, b0.z, b0.w, b1.x, b1.y, b1.z, b1.w};
        #pragma unroll
        for (int r = 0; r < 8; ++r)
            #pragma unroll
            for (int c = 0; c < 8; ++c) acc[r][c] += av[r] * bw[c];
    }

    #pragma unroll
    for (int r = 0; r < 8; ++r) {
        const float bv = __ldg(&bb[o0 + r]);
        #pragma unroll
        for (int c = 0; c < 8; ++c) acc[r][c] = (acc[r][c] + bv) * scale;
    }

    __syncthreads();
    float* nat = sm;
    #pragma unroll
    for (int r = 0; r < 8; ++r) {
        *(float4*)&nat[(o0 + r) * 132 + sA] = make_float4(acc[r][0], acc[r][1], acc[r][2], acc[r][3]);
        *(float4*)&nat[(o0 + r) * 132 + sB] = make_float4(acc[r][4], acc[r][5], acc[r][6], acc[r][7]);
    }
    __syncthreads();

    const int lane = t & 31, wid = t >> 5;
    const int rr = lane >> 2, cc = lane & 3;

    if (which == 0) {
        const size_t mbase = ((size_t)(row_base >> 4) + (size_t)wid) * 256;
        const int r0 = 16 * wid + rr;
        #pragma unroll
        for (int kk = 0; kk < 8; ++kk) {
            const int e0 = 16 * kk + 2 * cc;
            uint4 v;
            v.x = pack_h2(nat[e0 * 132 + r0],       nat[(e0 + 1) * 132 + r0]);
            v.y = pack_h2(nat[e0 * 132 + r0 + 8],   nat[(e0 + 1) * 132 + r0 + 8]);
            v.z = pack_h2(nat[(e0 + 8) * 132 + r0],     nat[(e0 + 9) * 132 + r0]);
            v.w = pack_h2(nat[(e0 + 8) * 132 + r0 + 8], nat[(e0 + 9) * 132 + r0 + 8]);
            g_Qp[mbase + (size_t)kk * 32 + lane] = v;
        }
    } else if (which == 1) {
        const int b = row_base / S_DIM, s_in = row_base % S_DIM, kt = s_in >> 7;
        const size_t tbase = (size_t)(b * 64 + kt) * 2048;
        #pragma unroll
        for (int jj = 0; jj < 2; ++jj) {
            const int j = 2 * wid + jj;
            const int srow = 8 * j + rr;
            #pragma unroll
            for (int kkp = 0; kkp < 4; ++kkp) {
                const int e0 = 32 * kkp + 2 * cc;
                const int e1 = e0 + 16;
                uint4 v;
                v.x = pack_h2(nat[e0 * 132 + srow],       nat[(e0 + 1) * 132 + srow]);
                v.y = pack_h2(nat[(e0 + 8) * 132 + srow], nat[(e0 + 9) * 132 + srow]);
                v.z = pack_h2(nat[e1 * 132 + srow],       nat[(e1 + 1) * 132 + srow]);
                v.w = pack_h2(nat[(e1 + 8) * 132 + srow], nat[(e1 + 9) * 132 + srow]);
                g_Kp[tbase + (size_t)j * 128 + kkp * 32 + lane] = v;
            }
        }
    } else {
        const int b = row_base / S_DIM, s_in = row_base % S_DIM, kt = s_in >> 7;
        const size_t tbase = (size_t)(b * 64 + kt) * 2048;
        #pragma unroll
        for (int jj = 0; jj < 2; ++jj) {
            const int j = 2 * wid + jj;
            const int erow = 8 * j + rr;
            #pragma unroll
            for (int kkp = 0; kkp < 4; ++kkp) {
                const int s0 = 32 * kkp + 2 * cc;
                const int s1 = s0 + 16;
                float2 p00 = *(const float2*)&nat[erow * 132 + s0];
                float2 p01 = *(const float2*)&nat[erow * 132 + s0 + 8];
                float2 p10 = *(const float2*)&nat[erow * 132 + s1];
                float2 p11 = *(const float2*)&nat[erow * 132 + s1 + 8];
                uint4 v;
                v.x = pack_h2(p00.x, p00.y);
                v.y = pack_h2(p01.x, p01.y);
                v.z = pack_h2(p10.x, p10.y);
                v.w = pack_h2(p11.x, p11.y);
                g_Vp[tbase + (size_t)j * 128 + kkp * 32 + lane] = v;
            }
        }
    }
}

// ===== fp16 flash attention: 4 row-groups x 2 kv-halves, register P =======
// grid (S/128, B), 256 threads = 8 warps. Warp (g = wid>>1, h = wid&1):
// q-rows [32g,32g+32), kv cols [64h,64h+64), partial O over full E.
// SMEM uint4: Kb[2][2048], Vb[2][2048]@4096, Qs[2048]@8192, rs floats @10240.
// Epilogue: h=1 stores partial O into Kb region (dead), h=0 combines.
__device__ __forceinline__ void prefetch_tile(uint32_t sb, int buf,
                                              const uint4* ksrc, const uint4* vsrc, int t) {
    const uint32_t kd = sb + (uint32_t)(buf * 2048) * 16u;
    const uint32_t vd = sb + (uint32_t)(4096 + buf * 2048) * 16u;
    #pragma unroll
    for (int i = 0; i < 8; ++i) {
        cp_async16(kd + (t + i * 256) * 16, ksrc + t + i * 256);
        cp_async16(vd + (t + i * 256) * 16, vsrc + t + i * 256);
    }
}

__global__ __launch_bounds__(256, 1) void attn_mma_kernel(float* __restrict__ out)
{
    extern __shared__ uint4 sb4[];
    uint4* Qs = sb4 + 8192;
    float* rs = (float*)(sb4 + 10240);   // [128 rows][2 halves]

    const int t = threadIdx.x;
    const int lane = t & 31, wid = t >> 5;
    const int rr = lane >> 2, cc = lane & 3;
    const int g = wid >> 1, h = wid & 1;
    const int b = blockIdx.y, q0 = blockIdx.x * 128;
    const uint32_t sb = smem_to_u32(sb4);

    // Q fragments -> SMEM (one-time)
    {
        const uint4* qsrc = &g_Qp[((size_t)(b * S_DIM + q0) >> 4) * 256];
        #pragma unroll
        for (int i = 0; i < 8; ++i) Qs[t + i * 256] = qsrc[t + i * 256];
    }

    float oacc[2][16][4];
    #pragma unroll
    for (int m = 0; m < 2; ++m)
        #pragma unroll
        for (int j = 0; j < 16; ++j)
            #pragma unroll
            for (int q = 0; q < 4; ++q) oacc[m][j][q] = 0.0f;
    float rsum[2][2] = {{0.0f, 0.0f}, {0.0f, 0.0f}};

    const uint4* kbase = &g_Kp[(size_t)(b * 64) * 2048];
    const uint4* vbase = &g_Vp[(size_t)(b * 64) * 2048];

    prefetch_tile(sb, 0, kbase, vbase, t);
    CP_COMMIT();

    const int mt0 = 2 * g, mt1 = 2 * g + 1;

    for (int kt = 0; kt < 64; ++kt) {
        __syncthreads();
        const int nkt = (kt + 1) & 63;
        prefetch_tile(sb, (kt + 1) & 1, kbase + (size_t)nkt * 2048,
                      vbase + (size_t)nkt * 2048, t);
        CP_COMMIT();
        CP_WAIT1();
        __syncthreads();

        const uint4* Kt = sb4 + (kt & 1) * 2048;
        const uint4* Vt = sb4 + 4096 + (kt & 1) * 2048;

        #pragma unroll
        for (int qq = 0; qq < 2; ++qq) {     // quarter: kv cols 64h+32qq..+31
            const int jbase = 8 * h + 4 * qq;
            const int kkpv  = 2 * h + qq;    // V's kv chunk for this quarter

            // ---- QK: 4 j-tiles x full E ----
            float f[2][4][4];
            #pragma unroll
            for (int m = 0; m < 2; ++m)
                #pragma unroll
                for (int jl = 0; jl < 4; ++jl)
                    #pragma unroll
                    for (int q = 0; q < 4; ++q) f[m][jl][q] = 0.0f;

            #pragma unroll
            for (int kkp = 0; kkp < 4; ++kkp) {
                uint4 q00 = Qs[(mt0 * 8 + 2 * kkp) * 32 + lane];
                uint4 q01 = Qs[(mt0 * 8 + 2 * kkp + 1) * 32 + lane];
                uint4 q10 = Qs[(mt1 * 8 + 2 * kkp) * 32 + lane];
                uint4 q11 = Qs[(mt1 * 8 + 2 * kkp + 1) * 32 + lane];
                uint32_t a00[4] = {q00.x, q00.y, q00.z, q00.w};
                uint32_t a01[4] = {q01.x, q01.y, q01.z, q01.w};
                uint32_t a10[4] = {q10.x, q10.y, q10.z, q10.w};
                uint32_t a11[4] = {q11.x, q11.y, q11.z, q11.w};
                #pragma unroll
                for (int jl = 0; jl < 4; ++jl) {
                    uint4 bv = Kt[((jbase + jl) * 4 + kkp) * 32 + lane];
                    uint32_t b0[2] = {bv.x, bv.y}, b1[2] = {bv.z, bv.w};
                    mma_f16(f[0][jl], a00, b0);
                    mma_f16(f[0][jl], a01, b1);
                    mma_f16(f[1][jl], a10, b0);
                    mma_f16(f[1][jl], a11, b1);
                }
            }

            // ---- P = exp2(S) in registers; rsum on rounded values ----
            uint32_t ph[2][4][2];
            #pragma unroll
            for (int m = 0; m < 2; ++m)
                #pragma unroll
                for (int jl = 0; jl < 4; ++jl) {
                    __half2 h01 = __floats2half2_rn(ex2f(f[m][jl][0]), ex2f(f[m][jl][1]));
                    __half2 h23 = __floats2half2_rn(ex2f(f[m][jl][2]), ex2f(f[m][jl][3]));
                    float2 p01 = __half22float2(h01);
                    float2 p23 = __half22float2(h23);
                    rsum[m][0] += p01.x + p01.y;
                    rsum[m][1] += p23.x + p23.y;
                    ph[m][jl][0] = *reinterpret_cast<uint32_t*>(&h01);
                    ph[m][jl][1] = *reinterpret_cast<uint32_t*>(&h23);
                }

            // ---- O += P_quarter V_quarter (k = 32 kv rows = kkpv) ----
            uint32_t a0m0[4] = {ph[0][0][0], ph[0][0][1], ph[0][1][0], ph[0][1][1]};
            uint32_t a1m0[4] = {ph[0][2][0], ph[0][2][1], ph[0][3][0], ph[0][3][1]};
            uint32_t a0m1[4] = {ph[1][0][0], ph[1][0][1], ph[1][1][0], ph[1][1][1]};
            uint32_t a1m1[4] = {ph[1][2][0], ph[1][2][1], ph[1][3][0], ph[1][3][1]};
            #pragma unroll
            for (int j = 0; j < 16; ++j) {
                uint4 bv = Vt[(j * 4 + kkpv) * 32 + lane];
                uint32_t b0[2] = {bv.x, bv.y}, b1[2] = {bv.z, bv.w};
                mma_f16(oacc[0][j], a0m0, b0);
                mma_f16(oacc[0][j], a1m0, b1);
                mma_f16(oacc[1][j], a0m1, b0);
                mma_f16(oacc[1][j], a1m1, b1);
            }
        }
    }

    // ---- rsum: quad-reduce, publish per half ----
    #pragma unroll
    for (int m = 0; m < 2; ++m)
        #pragma unroll
        for (int s2 = 0; s2 < 2; ++s2) {
            float v = rsum[m][s2];
            v += __shfl_xor_sync(0xffffffffu, v, 1);
            v += __shfl_xor_sync(0xffffffffu, v, 2);
            rsum[m][s2] = v;
        }
    __syncthreads();   // last tile's compute done; Kb region now dead
    if (cc == 0) {
        #pragma unroll
        for (int m = 0; m < 2; ++m) {
            rs[(32 * g + 16 * m + rr) * 2 + h]     = rsum[m][0];
            rs[(32 * g + 16 * m + rr + 8) * 2 + h] = rsum[m][1];
        }
    }

    // ---- partial-O exchange: h=1 stores into Kb region ----
    float* Ox = (float*)sb4;   // 64KB: [(2g+m)*16 + j][lane*4]
    if (h == 1) {
        #pragma unroll
        for (int m = 0; m < 2; ++m)
            #pragma unroll
            for (int j = 0; j < 16; ++j)
                *(float4*)&Ox[(((2 * g + m) * 16 + j) * 32 + lane) * 4] =
                    make_float4(oacc[m][j][0], oacc[m][j][1], oacc[m][j][2], oacc[m][j][3]);
    }
    __syncthreads();

    if (h == 0) {
        #pragma unroll
        for (int m = 0; m < 2; ++m) {
            const int rl0 = 32 * g + 16 * m + rr;
            const float inv0 = 1.0f / (rs[rl0 * 2] + rs[rl0 * 2 + 1]);
            const float inv1 = 1.0f / (rs[(rl0 + 8) * 2] + rs[(rl0 + 8) * 2 + 1]);
            const size_t row0 = (size_t)b * S_DIM + q0 + rl0;
            #pragma unroll
            for (int j = 0; j < 16; ++j) {
                float4 o2 = *(const float4*)&Ox[(((2 * g + m) * 16 + j) * 32 + lane) * 4];
                const int e = 8 * j + 2 * cc;
                *(float2*)&out[row0 * E_DIM + e] =
                    make_float2((oacc[m][j][0] + o2.x) * inv0, (oacc[m][j][1] + o2.y) * inv0);
                *(float2*)&out[(row0 + 8) * E_DIM + e] =
                    make_float2((oacc[m][j][2] + o2.z) * inv1, (oacc[m][j][3] + o2.w) * inv1);
            }
        }
    }
}

// ============================== launch =====================================
extern "C" void kernel_launch(void* const* d_in, const int* in_sizes, int n_in,
                              void* d_out, int out_size)
{
    (void)in_sizes; (void)n_in; (void)out_size;
    const float* x  = (const float*)d_in[0];
    const float* Wq = (const float*)d_in[1];
    const float* bq = (const float*)d_in[2];
    const float* Wk = (const float*)d_in[3];
    const float* bk = (const float*)d_in[4];
    const float* Wv = (const float*)d_in[5];
    const float* bv = (const float*)d_in[6];
    float* out = (float*)d_out;

    const int attn_smem = 10240 * 16 + 1024;   // 164864 B

    cudaFuncSetAttribute(proj_kernel, cudaFuncAttributeMaxDynamicSharedMemorySize, 131072);
    cudaFuncSetAttribute(attn_mma_kernel, cudaFuncAttributeMaxDynamicSharedMemorySize, attn_smem);

    dim3 pg((B_DIM * S_DIM) / 128, 3);
    proj_kernel<<<pg, 256, 131072>>>(x, Wq, bq, Wk, bk, Wv, bv);

    dim3 ag(S_DIM / 128, B_DIM);
    attn_mma_kernel<<<ag, 256, attn_smem>>>(out);
}

// round 10
// speedup vs baseline: 1.2909x; 1.0784x over previous
#include <cuda_runtime.h>
#include <cuda_fp16.h>
#include <math.h>
#include <stdint.h>

#define B_DIM 2
#define S_DIM 8192
#define E_DIM 128

// fp16 fragment-permuted scratch (uint4 = 8 halves):
// g_Qp: per m-tile (16 q rows): [kk 0..7][lane] -> A-frag m16n8k16 {a0,a1,a2,a3}
// g_Kp: per kv-tile: [j 0..15][kkp 0..3][lane] -> {b0(2kkp),b1(2kkp),b0(2kkp+1),b1(2kkp+1)}, n=kv, k=E
// g_Vp: per kv-tile: [j(e) 0..15][kkp(kv) 0..3][lane] -> same, n=E, k=kv
__device__ uint4 g_Qp[B_DIM * S_DIM * E_DIM / 8];
__device__ uint4 g_Kp[B_DIM * S_DIM * E_DIM / 8];
__device__ uint4 g_Vp[B_DIM * S_DIM * E_DIM / 8];

__device__ __forceinline__ uint32_t smem_to_u32(const void* p) {
    uint32_t a;
    asm("{ .reg .u64 t; cvta.to.shared.u64 t, %1; cvt.u32.u64 %0, t; }" : "=r"(a) : "l"(p));
    return a;
}
__device__ __forceinline__ void mma_f16(float* d, const uint32_t* a, const uint32_t* b) {
    asm volatile(
        "mma.sync.aligned.m16n8k16.row.col.f32.f16.f16.f32 "
        "{%0,%1,%2,%3}, {%4,%5,%6,%7}, {%8,%9}, {%0,%1,%2,%3};"
        : "+f"(d[0]), "+f"(d[1]), "+f"(d[2]), "+f"(d[3])
        : "r"(a[0]), "r"(a[1]), "r"(a[2]), "r"(a[3]), "r"(b[0]), "r"(b[1]));
}
__device__ __forceinline__ uint32_t pack_h2(float lo, float hi) {
    __half2 h = __floats2half2_rn(lo, hi);
    return *reinterpret_cast<uint32_t*>(&h);
}
// exp2 on packed fp16 pair: one MUFU op for two values
__device__ __forceinline__ uint32_t ex2_h2(float lo, float hi) {
    __half2 s = __floats2half2_rn(lo, hi);
    uint32_t si = *reinterpret_cast<uint32_t*>(&s);
    uint32_t r;
    asm("ex2.approx.f16x2 %0, %1;" : "=r"(r) : "r"(si));
    return r;
}
__device__ __forceinline__ void cp_async16(uint32_t saddr, const void* g) {
    asm volatile("cp.async.cg.shared.global [%0], [%1], 16;" :: "r"(saddr), "l"(g));
}
#define CP_COMMIT() asm volatile("cp.async.commit_group;" ::: "memory")
#define CP_WAIT1()  asm volatile("cp.async.wait_group 1;" ::: "memory")

// ======================= projection (scalar fp32 core) =====================
// grid = ((B*S)/128, 3): which 0->Q (pre-scaled by log2e/sqrt(E)), 1->K, 2->V.
__global__ __launch_bounds__(256) void proj_kernel(
    const float* __restrict__ x,
    const float* __restrict__ Wq, const float* __restrict__ bq,
    const float* __restrict__ Wk, const float* __restrict__ bk,
    const float* __restrict__ Wv, const float* __restrict__ bvp)
{
    extern __shared__ float sm[];
    float* xs = sm;              // [e][s] 128x128
    float* ws = sm + 128 * 128;  // [e][o] 128x128

    const int t = threadIdx.x;
    const int which = blockIdx.y;
    const float* __restrict__ W  = (which == 0) ? Wq : (which == 1) ? Wk : Wv;
    const float* __restrict__ bb = (which == 0) ? bq : (which == 1) ? bk : bvp;
    const float scale = (which == 0) ? (0.08838834764831845f * 1.4426950408889634f) : 1.0f;

    const int row_base = blockIdx.x * 128;
    const int rm = t & 7, cm = t >> 3, c0 = 4 * cm;
    #pragma unroll
    for (int p = 0; p < 4; ++p) {
        const int r0 = 32 * p + 4 * rm;
        float4 v0 = *(const float4*)&x[(row_base + r0 + 0) * E_DIM + c0];
        float4 v1 = *(const float4*)&x[(row_base + r0 + 1) * E_DIM + c0];
        float4 v2 = *(const float4*)&x[(row_base + r0 + 2) * E_DIM + c0];
        float4 v3 = *(const float4*)&x[(row_base + r0 + 3) * E_DIM + c0];
        *(float4*)&xs[(c0 + 0) * 128 + r0] = make_float4(v0.x, v1.x, v2.x, v3.x);
        *(float4*)&xs[(c0 + 1) * 128 + r0] = make_float4(v0.y, v1.y, v2.y, v3.y);
        *(float4*)&xs[(c0 + 2) * 128 + r0] = make_float4(v0.z, v1.z, v2.z, v3.z);
        *(float4*)&xs[(c0 + 3) * 128 + r0] = make_float4(v0.w, v1.w, v2.w, v3.w);
        float4 u0 = *(const float4*)&W[(r0 + 0) * E_DIM + c0];
        float4 u1 = *(const float4*)&W[(r0 + 1) * E_DIM + c0];
        float4 u2 = *(const float4*)&W[(r0 + 2) * E_DIM + c0];
        float4 u3 = *(const float4*)&W[(r0 + 3) * E_DIM + c0];
        *(float4*)&ws[(c0 + 0) * 128 + r0] = make_float4(u0.x, u1.x, u2.x, u3.x);
        *(float4*)&ws[(c0 + 1) * 128 + r0] = make_float4(u0.y, u1.y, u2.y, u3.y);
        *(float4*)&ws[(c0 + 2) * 128 + r0] = make_float4(u0.z, u1.z, u2.z, u3.z);
        *(float4*)&ws[(c0 + 3) * 128 + r0] = make_float4(u0.w, u1.w, u2.w, u3.w);
    }
    __syncthreads();

    const int og = t >> 4, sg = t & 15;
    const int o0 = 8 * og, sA = 4 * sg, sB = 64 + 4 * sg;

    float acc[8][8];
    #pragma unroll
    for (int r = 0; r < 8; ++r)
        #pragma unroll
        for (int c = 0; c < 8; ++c) acc[r][c] = 0.0f;

    #pragma unroll 8
    for (int e = 0; e < 128; ++e) {
        float4 a0 = *(const float4*)&ws[e * 128 + o0];
        float4 a1 = *(const float4*)&ws[e * 128 + o0 + 4];
        float4 b0 = *(const float4*)&xs[e * 128 + sA];
        float4 b1 = *(const float4*)&xs[e * 128 + sB];
        float av[8] = {a0.x, a0.y, a0.z, a0.w, a1.x, a1.y, a1.z, a1.w};
        float bw[8] = {b0.x, b0.y, b0.z, b0.w, b1.x, b1.y, b1.z, b1.w};
        #pragma unroll
        for (int r = 0; r < 8; ++r)
            #pragma unroll
            for (int c = 0; c < 8; ++c) acc[r][c] += av[r] * bw[c];
    }

    #pragma unroll
    for (int r = 0; r < 8; ++r) {
        const float bv = __ldg(&bb[o0 + r]);
        #pragma unroll
        for (int c = 0; c < 8; ++c) acc[r][c] = (acc[r][c] + bv) * scale;
    }

    __syncthreads();
    float* nat = sm;
    #pragma unroll
    for (int r = 0; r < 8; ++r) {
        *(float4*)&nat[(o0 + r) * 132 + sA] = make_float4(acc[r][0], acc[r][1], acc[r][2], acc[r][3]);
        *(float4*)&nat[(o0 + r) * 132 + sB] = make_float4(acc[r][4], acc[r][5], acc[r][6], acc[r][7]);
    }
    __syncthreads();

    const int lane = t & 31, wid = t >> 5;
    const int rr = lane >> 2, cc = lane & 3;

    if (which == 0) {
        const size_t mbase = ((size_t)(row_base >> 4) + (size_t)wid) * 256;
        const int r0 = 16 * wid + rr;
        #pragma unroll
        for (int kk = 0; kk < 8; ++kk) {
            const int e0 = 16 * kk + 2 * cc;
            uint4 v;
            v.x = pack_h2(nat[e0 * 132 + r0],       nat[(e0 + 1) * 132 + r0]);
            v.y = pack_h2(nat[e0 * 132 + r0 + 8],   nat[(e0 + 1) * 132 + r0 + 8]);
            v.z = pack_h2(nat[(e0 + 8) * 132 + r0],     nat[(e0 + 9) * 132 + r0]);
            v.w = pack_h2(nat[(e0 + 8) * 132 + r0 + 8], nat[(e0 + 9) * 132 + r0 + 8]);
            g_Qp[mbase + (size_t)kk * 32 + lane] = v;
        }
    } else if (which == 1) {
        const int b = row_base / S_DIM, s_in = row_base % S_DIM, kt = s_in >> 7;
        const size_t tbase = (size_t)(b * 64 + kt) * 2048;
        #pragma unroll
        for (int jj = 0; jj < 2; ++jj) {
            const int j = 2 * wid + jj;
            const int srow = 8 * j + rr;
            #pragma unroll
            for (int kkp = 0; kkp < 4; ++kkp) {
                const int e0 = 32 * kkp + 2 * cc;
                const int e1 = e0 + 16;
                uint4 v;
                v.x = pack_h2(nat[e0 * 132 + srow],       nat[(e0 + 1) * 132 + srow]);
                v.y = pack_h2(nat[(e0 + 8) * 132 + srow], nat[(e0 + 9) * 132 + srow]);
                v.z = pack_h2(nat[e1 * 132 + srow],       nat[(e1 + 1) * 132 + srow]);
                v.w = pack_h2(nat[(e1 + 8) * 132 + srow], nat[(e1 + 9) * 132 + srow]);
                g_Kp[tbase + (size_t)j * 128 + kkp * 32 + lane] = v;
            }
        }
    } else {
        const int b = row_base / S_DIM, s_in = row_base % S_DIM, kt = s_in >> 7;
        const size_t tbase = (size_t)(b * 64 + kt) * 2048;
        #pragma unroll
        for (int jj = 0; jj < 2; ++jj) {
            const int j = 2 * wid + jj;
            const int erow = 8 * j + rr;
            #pragma unroll
            for (int kkp = 0; kkp < 4; ++kkp) {
                const int s0 = 32 * kkp + 2 * cc;
                const int s1 = s0 + 16;
                float2 p00 = *(const float2*)&nat[erow * 132 + s0];
                float2 p01 = *(const float2*)&nat[erow * 132 + s0 + 8];
                float2 p10 = *(const float2*)&nat[erow * 132 + s1];
                float2 p11 = *(const float2*)&nat[erow * 132 + s1 + 8];
                uint4 v;
                v.x = pack_h2(p00.x, p00.y);
                v.y = pack_h2(p01.x, p01.y);
                v.z = pack_h2(p10.x, p10.y);
                v.w = pack_h2(p11.x, p11.y);
                g_Vp[tbase + (size_t)j * 128 + kkp * 32 + lane] = v;
            }
        }
    }
}

// ================= fp16 mma.sync flash attention (FA2 P-reuse) =============
// grid (S/128, B), 256 threads = 8 warps; warp w owns m-tile w (16 q rows) x
// all 128 kv columns. Q in registers, P never leaves registers.
// Row-sum computed on the tensor pipe via a register-constant ones B-frag.
__device__ __forceinline__ void prefetch_tile(uint32_t sdst, const uint4* ksrc,
                                              const uint4* vsrc, int t) {
    #pragma unroll
    for (int i = 0; i < 8; ++i) {
        const int s = t + i * 256;
        cp_async16(sdst + s * 16, ksrc + s);
        cp_async16(sdst + 32768 + s * 16, vsrc + s);
    }
}

__global__ __launch_bounds__(256, 1) void attn_mma_kernel(float* __restrict__ out)
{
    extern __shared__ uint4 sbuf[];   // [2][4096]: per buffer K[0,2048) V[2048,4096)
    const int t = threadIdx.x;
    const int lane = t & 31, wid = t >> 5;
    const int rr = lane >> 2, cc = lane & 3;
    const int b = blockIdx.y, q0 = blockIdx.x * 128;
    const uint32_t sb = smem_to_u32(sbuf);

    // ---- Q A-frags into registers (loop-invariant) ----
    uint32_t Qa[8][4];
    {
        const uint4* qsrc = &g_Qp[(((size_t)(b * S_DIM + q0) >> 4) + (size_t)wid) * 256];
        #pragma unroll
        for (int kk = 0; kk < 8; ++kk) {
            uint4 v = qsrc[kk * 32 + lane];
            Qa[kk][0] = v.x; Qa[kk][1] = v.y; Qa[kk][2] = v.z; Qa[kk][3] = v.w;
        }
    }

    float oacc[16][4];
    #pragma unroll
    for (int j = 0; j < 16; ++j)
        #pragma unroll
        for (int q = 0; q < 4; ++q) oacc[j][q] = 0.0f;

    // rsum accumulator on tensor pipe: oe = P @ ones (column 0 of a virtual tile)
    float oe[4] = {0.0f, 0.0f, 0.0f, 0.0f};
    const uint32_t onesc = (rr == 0) ? 0x3C003C00u : 0u;   // fp16 1.0 pair on n-col 0
    uint32_t bOnes[2] = {onesc, onesc};

    const uint4* kbase = &g_Kp[(size_t)(b * 64) * 2048];
    const uint4* vbase = &g_Vp[(size_t)(b * 64) * 2048];

    prefetch_tile(sb, kbase, vbase, t);   // tile 0 -> buf 0
    CP_COMMIT();

    for (int kt = 0; kt < 64; ++kt) {
        __syncthreads();   // prior compute done: buf[(kt+1)&1] free for overwrite
        const int nkt = (kt + 1) & 63;
        prefetch_tile(sb + ((kt + 1) & 1) * 65536,
                      kbase + (size_t)nkt * 2048, vbase + (size_t)nkt * 2048, t);
        CP_COMMIT();
        CP_WAIT1();        // tile kt's group complete
        __syncthreads();   // all threads' copies visible

        const uint4* Ks = sbuf + (kt & 1) * 4096;
        const uint4* Vs = Ks + 2048;

        // ---- S = Q K^T, P = exp2(S) in registers (f16x2 MUFU) ----
        uint32_t ph[16][2];
        #pragma unroll
        for (int j = 0; j < 16; ++j) {
            float f[4] = {0.0f, 0.0f, 0.0f, 0.0f};
            #pragma unroll
            for (int kkp = 0; kkp < 4; ++kkp) {
                uint4 bv = Ks[j * 128 + kkp * 32 + lane];
                uint32_t b0[2] = {bv.x, bv.y}, b1[2] = {bv.z, bv.w};
                mma_f16(f, Qa[2 * kkp], b0);
                mma_f16(f, Qa[2 * kkp + 1], b1);
            }
            ph[j][0] = ex2_h2(f[0], f[1]);
            ph[j][1] = ex2_h2(f[2], f[3]);
        }

        // ---- O += P V ; rsum += P @ ones (both on tensor pipe) ----
        #pragma unroll
        for (int j = 0; j < 16; ++j) {
            #pragma unroll
            for (int kkp = 0; kkp < 4; ++kkp) {
                uint4 bv = Vs[j * 128 + kkp * 32 + lane];
                uint32_t a0[4] = {ph[4 * kkp][0],     ph[4 * kkp][1],
                                  ph[4 * kkp + 1][0], ph[4 * kkp + 1][1]};
                uint32_t a1[4] = {ph[4 * kkp + 2][0], ph[4 * kkp + 2][1],
                                  ph[4 * kkp + 3][0], ph[4 * kkp + 3][1]};
                uint32_t b0[2] = {bv.x, bv.y}, b1[2] = {bv.z, bv.w};
                mma_f16(oacc[j], a0, b0);
                mma_f16(oacc[j], a1, b1);
            }
        }
        #pragma unroll
        for (int kkp = 0; kkp < 4; ++kkp) {
            uint32_t a0[4] = {ph[4 * kkp][0],     ph[4 * kkp][1],
                              ph[4 * kkp + 1][0], ph[4 * kkp + 1][1]};
            uint32_t a1[4] = {ph[4 * kkp + 2][0], ph[4 * kkp + 2][1],
                              ph[4 * kkp + 3][0], ph[4 * kkp + 3][1]};
            mma_f16(oe, a0, bOnes);
            mma_f16(oe, a1, bOnes);
        }
    }

    // ---- row sums live in oe[0]/oe[2] of cc==0 lanes; broadcast to quad ----
    const float s0 = __shfl_sync(0xffffffffu, oe[0], lane & 28);
    const float s1 = __shfl_sync(0xffffffffu, oe[2], lane & 28);
    const float inv0 = 1.0f / s0;
    const float inv1 = 1.0f / s1;

    const size_t row0 = (size_t)b * S_DIM + q0 + 16 * wid + rr;
    #pragma unroll
    for (int j = 0; j < 16; ++j) {
        const int e = 8 * j + 2 * cc;
        *(float2*)&out[row0 * E_DIM + e] =
            make_float2(oacc[j][0] * inv0, oacc[j][1] * inv0);
        *(float2*)&out[(row0 + 8) * E_DIM + e] =
            make_float2(oacc[j][2] * inv1, oacc[j][3] * inv1);
    }
}

// ============================== launch =====================================
extern "C" void kernel_launch(void* const* d_in, const int* in_sizes, int n_in,
                              void* d_out, int out_size)
{
    (void)in_sizes; (void)n_in; (void)out_size;
    const float* x  = (const float*)d_in[0];
    const float* Wq = (const float*)d_in[1];
    const float* bq = (const float*)d_in[2];
    const float* Wk = (const float*)d_in[3];
    const float* bk = (const float*)d_in[4];
    const float* Wv = (const float*)d_in[5];
    const float* bv = (const float*)d_in[6];
    float* out = (float*)d_out;

    cudaFuncSetAttribute(proj_kernel, cudaFuncAttributeMaxDynamicSharedMemorySize, 131072);
    cudaFuncSetAttribute(attn_mma_kernel, cudaFuncAttributeMaxDynamicSharedMemorySize, 131072);

    dim3 pg((B_DIM * S_DIM) / 128, 3);
    proj_kernel<<<pg, 256, 131072>>>(x, Wq, bq, Wk, bk, Wv, bv);

    dim3 ag(S_DIM / 128, B_DIM);
    attn_mma_kernel<<<ag, 256, 131072>>>(out);
}

// round 11
// speedup vs baseline: 1.4970x; 1.1596x over previous
#include <cuda_runtime.h>
#include <cuda_fp16.h>
#include <math.h>
#include <stdint.h>

#define B_DIM 2
#define S_DIM 8192
#define E_DIM 128

// fp16 fragment-permuted scratch (uint4 = 8 halves):
// g_Qp: per m-tile (16 q rows): [kk 0..7][lane] -> A-frag m16n8k16 {a0,a1,a2,a3}
// g_Kp: per kv-tile: [j 0..15][kkp 0..3][lane] -> {b0(2kkp),b1(2kkp),b0(2kkp+1),b1(2kkp+1)}, n=kv, k=E
// g_Vp: per kv-tile: [j(e) 0..15][kkp(kv) 0..3][lane] -> same, n=E, k=kv
__device__ uint4 g_Qp[B_DIM * S_DIM * E_DIM / 8];
__device__ uint4 g_Kp[B_DIM * S_DIM * E_DIM / 8];
__device__ uint4 g_Vp[B_DIM * S_DIM * E_DIM / 8];

__device__ __forceinline__ uint32_t smem_to_u32(const void* p) {
    uint32_t a;
    asm("{ .reg .u64 t; cvta.to.shared.u64 t, %1; cvt.u32.u64 %0, t; }" : "=r"(a) : "l"(p));
    return a;
}
__device__ __forceinline__ void mma_f16(float* d, const uint32_t* a, const uint32_t* b) {
    asm volatile(
        "mma.sync.aligned.m16n8k16.row.col.f32.f16.f16.f32 "
        "{%0,%1,%2,%3}, {%4,%5,%6,%7}, {%8,%9}, {%0,%1,%2,%3};"
        : "+f"(d[0]), "+f"(d[1]), "+f"(d[2]), "+f"(d[3])
        : "r"(a[0]), "r"(a[1]), "r"(a[2]), "r"(a[3]), "r"(b[0]), "r"(b[1]));
}
__device__ __forceinline__ uint32_t pack_h2(float lo, float hi) {
    __half2 h = __floats2half2_rn(lo, hi);
    return *reinterpret_cast<uint32_t*>(&h);
}
// exp2 on packed fp16 pair: one MUFU op for two values
__device__ __forceinline__ uint32_t ex2_h2(float lo, float hi) {
    __half2 s = __floats2half2_rn(lo, hi);
    uint32_t si = *reinterpret_cast<uint32_t*>(&s);
    uint32_t r;
    asm("ex2.approx.f16x2 %0, %1;" : "=r"(r) : "r"(si));
    return r;
}
__device__ __forceinline__ void cp_async16(uint32_t saddr, const void* g) {
    asm volatile("cp.async.cg.shared.global [%0], [%1], 16;" :: "r"(saddr), "l"(g));
}
#define CP_COMMIT() asm volatile("cp.async.commit_group;" ::: "memory")
#define CP_WAIT1()  asm volatile("cp.async.wait_group 1;" ::: "memory")

// ================= projection v2: fp16 tensor-core GEMM ====================
// grid = ((B*S)/128, 3): which 0->Q (scaled by log2e/sqrt(E)), 1->K, 2->V.
// Per CTA: X tile (128 rows) fp32 -> SMEM -> fp16 A-frags in regs;
// W -> fp16 B-frags in SMEM; 8 warps x (16 rows x 128 outs) via mma.
// Q/K epilogues are register-only (accumulator pairs == target fragment
// half2 pairs); V stages through SMEM [e][s] fp16 for its transpose.
__global__ __launch_bounds__(256) void proj_kernel(
    const float* __restrict__ x,
    const float* __restrict__ Wq, const float* __restrict__ bq,
    const float* __restrict__ Wk, const float* __restrict__ bk,
    const float* __restrict__ Wv, const float* __restrict__ bvp)
{
    extern __shared__ float sm[];
    float* nat = sm;                           // [s 128][e, stride 132] fp32
    uint4* Wf  = (uint4*)(sm + 128 * 132);     // [jn 16][kkp 4][lane 32]

    const int t = threadIdx.x;
    const int which = blockIdx.y;
    const float* __restrict__ W  = (which == 0) ? Wq : (which == 1) ? Wk : Wv;
    const float* __restrict__ bb = (which == 0) ? bq : (which == 1) ? bk : bvp;
    const float kscale = 0.08838834764831845f * 1.4426950408889634f;

    const int row_base = blockIdx.x * 128;
    const int lane = t & 31, wid = t >> 5;
    const int rr = lane >> 2, cc = lane & 3;

    // ---- X tile -> nat [s][e] (coalesced LDG.128 / STS.128) ----
    #pragma unroll
    for (int i = 0; i < 16; ++i) {
        const int f = t + i * 256;
        const int row = f >> 5, c4 = (f & 31) * 4;
        *(float4*)&nat[row * 132 + c4] =
            *(const float4*)&x[(size_t)(row_base + row) * E_DIM + c4];
    }
    // ---- W B-frags (warp wid builds jn = 2wid, 2wid+1; W is L2-hot) ----
    #pragma unroll
    for (int jj = 0; jj < 2; ++jj) {
        const int jn = 2 * wid + jj;
        const int n0 = 8 * jn + rr;
        #pragma unroll
        for (int kkp = 0; kkp < 4; ++kkp) {
            const int e0 = 32 * kkp + 2 * cc;
            uint4 v;
            v.x = pack_h2(W[n0 * 128 + e0],      W[n0 * 128 + e0 + 1]);
            v.y = pack_h2(W[n0 * 128 + e0 + 8],  W[n0 * 128 + e0 + 9]);
            v.z = pack_h2(W[n0 * 128 + e0 + 16], W[n0 * 128 + e0 + 17]);
            v.w = pack_h2(W[n0 * 128 + e0 + 24], W[n0 * 128 + e0 + 25]);
            Wf[(jn * 4 + kkp) * 32 + lane] = v;
        }
    }
    __syncthreads();

    // ---- X A-frags into registers (rows 16wid..16wid+15) ----
    uint32_t Xa[8][4];
    const int r0 = 16 * wid + rr;
    #pragma unroll
    for (int kk = 0; kk < 8; ++kk) {
        const int e0 = 16 * kk + 2 * cc;
        Xa[kk][0] = pack_h2(nat[r0 * 132 + e0],           nat[r0 * 132 + e0 + 1]);
        Xa[kk][1] = pack_h2(nat[(r0 + 8) * 132 + e0],     nat[(r0 + 8) * 132 + e0 + 1]);
        Xa[kk][2] = pack_h2(nat[r0 * 132 + e0 + 8],       nat[r0 * 132 + e0 + 9]);
        Xa[kk][3] = pack_h2(nat[(r0 + 8) * 132 + e0 + 8], nat[(r0 + 8) * 132 + e0 + 9]);
    }
    __syncthreads();   // nat now dead -> reused as V staging for which==2

    __half* Vst = (__half*)sm;   // [e 128][s, stride 132] fp16
    const int b = row_base / S_DIM, s_in = row_base % S_DIM, kt = s_in >> 7;
    const size_t tbase = (size_t)(b * 64 + kt) * 2048;

    #pragma unroll
    for (int jg = 0; jg < 4; ++jg) {   // group of 4 n-jtiles = 32 output cols
        float f4[4][4];
        #pragma unroll
        for (int jl = 0; jl < 4; ++jl)
            #pragma unroll
            for (int q = 0; q < 4; ++q) f4[jl][q] = 0.0f;

        #pragma unroll
        for (int jl = 0; jl < 4; ++jl) {
            const int jn = 4 * jg + jl;
            #pragma unroll
            for (int kkp = 0; kkp < 4; ++kkp) {
                uint4 bv = Wf[(jn * 4 + kkp) * 32 + lane];
                uint32_t b0[2] = {bv.x, bv.y}, b1[2] = {bv.z, bv.w};
                mma_f16(f4[jl], Xa[2 * kkp], b0);
                mma_f16(f4[jl], Xa[2 * kkp + 1], b1);
            }
            const float2 bias = *(const float2*)&bb[8 * jn + 2 * cc];
            f4[jl][0] += bias.x; f4[jl][1] += bias.y;
            f4[jl][2] += bias.x; f4[jl][3] += bias.y;
        }

        if (which == 0) {
            #pragma unroll
            for (int jl = 0; jl < 4; ++jl)
                #pragma unroll
                for (int q = 0; q < 4; ++q) f4[jl][q] *= kscale;
            const size_t mbase = ((size_t)(row_base >> 4) + (size_t)wid) * 256;
            uint4 v0, v1;   // kk = 2jg (jn pair 4jg,4jg+1), kk = 2jg+1 (4jg+2,4jg+3)
            v0.x = pack_h2(f4[0][0], f4[0][1]);
            v0.y = pack_h2(f4[0][2], f4[0][3]);
            v0.z = pack_h2(f4[1][0], f4[1][1]);
            v0.w = pack_h2(f4[1][2], f4[1][3]);
            g_Qp[mbase + (size_t)(2 * jg) * 32 + lane] = v0;
            v1.x = pack_h2(f4[2][0], f4[2][1]);
            v1.y = pack_h2(f4[2][2], f4[2][3]);
            v1.z = pack_h2(f4[3][0], f4[3][1]);
            v1.w = pack_h2(f4[3][2], f4[3][3]);
            g_Qp[mbase + (size_t)(2 * jg + 1) * 32 + lane] = v1;
        } else if (which == 1) {
            uint4 v0, v1;   // kv j = 2wid (rows rr), 2wid+1 (rows rr+8); kkp = jg
            v0.x = pack_h2(f4[0][0], f4[0][1]);
            v0.y = pack_h2(f4[1][0], f4[1][1]);
            v0.z = pack_h2(f4[2][0], f4[2][1]);
            v0.w = pack_h2(f4[3][0], f4[3][1]);
            g_Kp[tbase + (size_t)(2 * wid) * 128 + jg * 32 + lane] = v0;
            v1.x = pack_h2(f4[0][2], f4[0][3]);
            v1.y = pack_h2(f4[1][2], f4[1][3]);
            v1.z = pack_h2(f4[2][2], f4[2][3]);
            v1.w = pack_h2(f4[3][2], f4[3][3]);
            g_Kp[tbase + (size_t)(2 * wid + 1) * 128 + jg * 32 + lane] = v1;
        } else {
            #pragma unroll
            for (int jl = 0; jl < 4; ++jl) {
                const int e0 = 8 * (4 * jg + jl) + 2 * cc;
                Vst[e0 * 132 + r0]           = __float2half_rn(f4[jl][0]);
                Vst[(e0 + 1) * 132 + r0]     = __float2half_rn(f4[jl][1]);
                Vst[e0 * 132 + r0 + 8]       = __float2half_rn(f4[jl][2]);
                Vst[(e0 + 1) * 132 + r0 + 8] = __float2half_rn(f4[jl][3]);
            }
        }
    }

    if (which == 2) {   // V transpose pack from staged [e][s] fp16
        __syncthreads();
        #pragma unroll
        for (int jj = 0; jj < 2; ++jj) {
            const int j = 2 * wid + jj;
            const int erow = 8 * j + rr;
            #pragma unroll
            for (int kkp = 0; kkp < 4; ++kkp) {
                const int s0 = 32 * kkp + 2 * cc;
                const int s1 = s0 + 16;
                uint4 v;
                v.x = *(const uint32_t*)&Vst[erow * 132 + s0];
                v.y = *(const uint32_t*)&Vst[erow * 132 + s0 + 8];
                v.z = *(const uint32_t*)&Vst[erow * 132 + s1];
                v.w = *(const uint32_t*)&Vst[erow * 132 + s1 + 8];
                g_Vp[tbase + (size_t)j * 128 + kkp * 32 + lane] = v;
            }
        }
    }
}

// ================= fp16 mma.sync flash attention (FA2 P-reuse) =============
// grid (S/128, B), 256 threads = 8 warps; warp w owns m-tile w (16 q rows) x
// all 128 kv columns. Q in registers, P never leaves registers.
// Mainloop chunked by 32 kv cols: scores -> exp -> ones-MMA -> PV per chunk
// (small live set, LDS/MUFU/HMMA of adjacent chunks interleave).
__device__ __forceinline__ void prefetch_tile(uint32_t sdst, const uint4* ksrc,
                                              const uint4* vsrc, int t) {
    #pragma unroll
    for (int i = 0; i < 8; ++i) {
        const int s = t + i * 256;
        cp_async16(sdst + s * 16, ksrc + s);
        cp_async16(sdst + 32768 + s * 16, vsrc + s);
    }
}

__global__ __launch_bounds__(256, 1) void attn_mma_kernel(float* __restrict__ out)
{
    extern __shared__ uint4 sbuf[];   // [2][4096]: per buffer K[0,2048) V[2048,4096)
    const int t = threadIdx.x;
    const int lane = t & 31, wid = t >> 5;
    const int rr = lane >> 2, cc = lane & 3;
    const int b = blockIdx.y, q0 = blockIdx.x * 128;
    const uint32_t sb = smem_to_u32(sbuf);

    // ---- Q A-frags into registers (loop-invariant) ----
    uint32_t Qa[8][4];
    {
        const uint4* qsrc = &g_Qp[(((size_t)(b * S_DIM + q0) >> 4) + (size_t)wid) * 256];
        #pragma unroll
        for (int kk = 0; kk < 8; ++kk) {
            uint4 v = qsrc[kk * 32 + lane];
            Qa[kk][0] = v.x; Qa[kk][1] = v.y; Qa[kk][2] = v.z; Qa[kk][3] = v.w;
        }
    }

    float oacc[16][4];
    #pragma unroll
    for (int j = 0; j < 16; ++j)
        #pragma unroll
        for (int q = 0; q < 4; ++q) oacc[j][q] = 0.0f;

    // rsum accumulator on tensor pipe: oe = P @ ones (column 0 of a virtual tile)
    float oe[4] = {0.0f, 0.0f, 0.0f, 0.0f};
    const uint32_t onesc = (rr == 0) ? 0x3C003C00u : 0u;   // fp16 1.0 pair on n-col 0
    uint32_t bOnes[2] = {onesc, onesc};

    const uint4* kbase = &g_Kp[(size_t)(b * 64) * 2048];
    const uint4* vbase = &g_Vp[(size_t)(b * 64) * 2048];

    prefetch_tile(sb, kbase, vbase, t);   // tile 0 -> buf 0
    CP_COMMIT();

    for (int kt = 0; kt < 64; ++kt) {
        __syncthreads();   // prior compute done: buf[(kt+1)&1] free for overwrite
        const int nkt = (kt + 1) & 63;
        prefetch_tile(sb + ((kt + 1) & 1) * 65536,
                      kbase + (size_t)nkt * 2048, vbase + (size_t)nkt * 2048, t);
        CP_COMMIT();
        CP_WAIT1();        // tile kt's group complete
        __syncthreads();   // all threads' copies visible

        const uint4* Ks = sbuf + (kt & 1) * 4096;
        const uint4* Vs = Ks + 2048;

        #pragma unroll
        for (int kkp = 0; kkp < 4; ++kkp) {   // kv chunk: cols 32kkp..32kkp+31
            // ---- scores for 4 j-tiles of this chunk ----
            float f4[4][4];
            #pragma unroll
            for (int jl = 0; jl < 4; ++jl)
                #pragma unroll
                for (int q = 0; q < 4; ++q) f4[jl][q] = 0.0f;

            #pragma unroll
            for (int jl = 0; jl < 4; ++jl) {
                const int j = 4 * kkp + jl;
                #pragma unroll
                for (int ke = 0; ke < 4; ++ke) {
                    uint4 bv = Ks[j * 128 + ke * 32 + lane];
                    uint32_t b0[2] = {bv.x, bv.y}, b1[2] = {bv.z, bv.w};
                    mma_f16(f4[jl], Qa[2 * ke], b0);
                    mma_f16(f4[jl], Qa[2 * ke + 1], b1);
                }
            }

            // ---- P = exp2(S) (f16x2 MUFU), A-frags assembled in regs ----
            uint32_t ph[4][2];
            #pragma unroll
            for (int jl = 0; jl < 4; ++jl) {
                ph[jl][0] = ex2_h2(f4[jl][0], f4[jl][1]);
                ph[jl][1] = ex2_h2(f4[jl][2], f4[jl][3]);
            }
            uint32_t a0[4] = {ph[0][0], ph[0][1], ph[1][0], ph[1][1]};
            uint32_t a1[4] = {ph[2][0], ph[2][1], ph[3][0], ph[3][1]};

            // ---- rsum += P @ ones ; O += P V (all tensor pipe) ----
            mma_f16(oe, a0, bOnes);
            mma_f16(oe, a1, bOnes);
            #pragma unroll
            for (int je = 0; je < 16; ++je) {
                uint4 bv = Vs[je * 128 + kkp * 32 + lane];
                uint32_t b0[2] = {bv.x, bv.y}, b1[2] = {bv.z, bv.w};
                mma_f16(oacc[je], a0, b0);
                mma_f16(oacc[je], a1, b1);
            }
        }
    }

    // ---- row sums live in oe[0]/oe[2] of cc==0 lanes; broadcast to quad ----
    const float s0 = __shfl_sync(0xffffffffu, oe[0], lane & 28);
    const float s1 = __shfl_sync(0xffffffffu, oe[2], lane & 28);
    const float inv0 = 1.0f / s0;
    const float inv1 = 1.0f / s1;

    const size_t row0 = (size_t)b * S_DIM + q0 + 16 * wid + rr;
    #pragma unroll
    for (int j = 0; j < 16; ++j) {
        const int e = 8 * j + 2 * cc;
        *(float2*)&out[row0 * E_DIM + e] =
            make_float2(oacc[j][0] * inv0, oacc[j][1] * inv0);
        *(float2*)&out[(row0 + 8) * E_DIM + e] =
            make_float2(oacc[j][2] * inv1, oacc[j][3] * inv1);
    }
}

// ============================== launch =====================================
extern "C" void kernel_launch(void* const* d_in, const int* in_sizes, int n_in,
                              void* d_out, int out_size)
{
    (void)in_sizes; (void)n_in; (void)out_size;
    const float* x  = (const float*)d_in[0];
    const float* Wq = (const float*)d_in[1];
    const float* bq = (const float*)d_in[2];
    const float* Wk = (const float*)d_in[3];
    const float* bk = (const float*)d_in[4];
    const float* Wv = (const float*)d_in[5];
    const float* bv = (const float*)d_in[6];
    float* out = (float*)d_out;

    const int proj_smem = 128 * 132 * 4 + 2048 * 16;   // 100352 B

    cudaFuncSetAttribute(proj_kernel, cudaFuncAttributeMaxDynamicSharedMemorySize, proj_smem);
    cudaFuncSetAttribute(attn_mma_kernel, cudaFuncAttributeMaxDynamicSharedMemorySize, 131072);

    dim3 pg((B_DIM * S_DIM) / 128, 3);
    proj_kernel<<<pg, 256, proj_smem>>>(x, Wq, bq, Wk, bk, Wv, bv);

    dim3 ag(S_DIM / 128, B_DIM);
    attn_mma_kernel<<<ag, 256, 131072>>>(out);
}

// round 12
// speedup vs baseline: 1.5592x; 1.0416x over previous
#include <cuda_runtime.h>
#include <cuda_fp16.h>
#include <math.h>
#include <stdint.h>

#define B_DIM 2
#define S_DIM 8192
#define E_DIM 128

// fp16 fragment-permuted scratch (uint4 = 8 halves):
// g_Qp: per m-tile (16 q rows): [kk 0..7][lane] -> A-frag m16n8k16 {a0,a1,a2,a3}
// g_Kp: per kv-tile: [j 0..15][kkp 0..3][lane] -> {b0(2kkp),b1(2kkp),b0(2kkp+1),b1(2kkp+1)}, n=kv, k=E
// g_Vp: per kv-tile: [j(e) 0..15][kkp(kv) 0..3][lane] -> same, n=E, k=kv
__device__ uint4 g_Qp[B_DIM * S_DIM * E_DIM / 8];
__device__ uint4 g_Kp[B_DIM * S_DIM * E_DIM / 8];
__device__ uint4 g_Vp[B_DIM * S_DIM * E_DIM / 8];

__device__ __forceinline__ uint32_t smem_to_u32(const void* p) {
    uint32_t a;
    asm("{ .reg .u64 t; cvta.to.shared.u64 t, %1; cvt.u32.u64 %0, t; }" : "=r"(a) : "l"(p));
    return a;
}
__device__ __forceinline__ void mma_f16(float* d, const uint32_t* a, const uint32_t* b) {
    asm volatile(
        "mma.sync.aligned.m16n8k16.row.col.f32.f16.f16.f32 "
        "{%0,%1,%2,%3}, {%4,%5,%6,%7}, {%8,%9}, {%0,%1,%2,%3};"
        : "+f"(d[0]), "+f"(d[1]), "+f"(d[2]), "+f"(d[3])
        : "r"(a[0]), "r"(a[1]), "r"(a[2]), "r"(a[3]), "r"(b[0]), "r"(b[1]));
}
__device__ __forceinline__ uint32_t pack_h2(float lo, float hi) {
    __half2 h = __floats2half2_rn(lo, hi);
    return *reinterpret_cast<uint32_t*>(&h);
}
// exp2 on packed fp16 pair: one MUFU op for two values
__device__ __forceinline__ uint32_t ex2_h2(float lo, float hi) {
    __half2 s = __floats2half2_rn(lo, hi);
    uint32_t si = *reinterpret_cast<uint32_t*>(&s);
    uint32_t r;
    asm("ex2.approx.f16x2 %0, %1;" : "=r"(r) : "r"(si));
    return r;
}
__device__ __forceinline__ void cp_async16(uint32_t saddr, const void* g) {
    asm volatile("cp.async.cg.shared.global [%0], [%1], 16;" :: "r"(saddr), "l"(g));
}
#define CP_COMMIT() asm volatile("cp.async.commit_group;" ::: "memory")
#define CP_WAIT1()  asm volatile("cp.async.wait_group 1;" ::: "memory")

// ================= projection: fp16 tensor-core GEMM =======================
// grid = ((B*S)/128, 3): which 0->Q (scaled by log2e/sqrt(E)), 1->K, 2->V.
__global__ __launch_bounds__(256) void proj_kernel(
    const float* __restrict__ x,
    const float* __restrict__ Wq, const float* __restrict__ bq,
    const float* __restrict__ Wk, const float* __restrict__ bk,
    const float* __restrict__ Wv, const float* __restrict__ bvp)
{
    extern __shared__ float sm[];
    float* nat = sm;                           // [s 128][e, stride 132] fp32
    uint4* Wf  = (uint4*)(sm + 128 * 132);     // [jn 16][kkp 4][lane 32]

    const int t = threadIdx.x;
    const int which = blockIdx.y;
    const float* __restrict__ W  = (which == 0) ? Wq : (which == 1) ? Wk : Wv;
    const float* __restrict__ bb = (which == 0) ? bq : (which == 1) ? bk : bvp;
    const float kscale = 0.08838834764831845f * 1.4426950408889634f;

    const int row_base = blockIdx.x * 128;
    const int lane = t & 31, wid = t >> 5;
    const int rr = lane >> 2, cc = lane & 3;

    #pragma unroll
    for (int i = 0; i < 16; ++i) {
        const int f = t + i * 256;
        const int row = f >> 5, c4 = (f & 31) * 4;
        *(float4*)&nat[row * 132 + c4] =
            *(const float4*)&x[(size_t)(row_base + row) * E_DIM + c4];
    }
    #pragma unroll
    for (int jj = 0; jj < 2; ++jj) {
        const int jn = 2 * wid + jj;
        const int n0 = 8 * jn + rr;
        #pragma unroll
        for (int kkp = 0; kkp < 4; ++kkp) {
            const int e0 = 32 * kkp + 2 * cc;
            uint4 v;
            v.x = pack_h2(W[n0 * 128 + e0],      W[n0 * 128 + e0 + 1]);
            v.y = pack_h2(W[n0 * 128 + e0 + 8],  W[n0 * 128 + e0 + 9]);
            v.z = pack_h2(W[n0 * 128 + e0 + 16], W[n0 * 128 + e0 + 17]);
            v.w = pack_h2(W[n0 * 128 + e0 + 24], W[n0 * 128 + e0 + 25]);
            Wf[(jn * 4 + kkp) * 32 + lane] = v;
        }
    }
    __syncthreads();

    uint32_t Xa[8][4];
    const int r0 = 16 * wid + rr;
    #pragma unroll
    for (int kk = 0; kk < 8; ++kk) {
        const int e0 = 16 * kk + 2 * cc;
        Xa[kk][0] = pack_h2(nat[r0 * 132 + e0],           nat[r0 * 132 + e0 + 1]);
        Xa[kk][1] = pack_h2(nat[(r0 + 8) * 132 + e0],     nat[(r0 + 8) * 132 + e0 + 1]);
        Xa[kk][2] = pack_h2(nat[r0 * 132 + e0 + 8],       nat[r0 * 132 + e0 + 9]);
        Xa[kk][3] = pack_h2(nat[(r0 + 8) * 132 + e0 + 8], nat[(r0 + 8) * 132 + e0 + 9]);
    }
    __syncthreads();   // nat now dead -> reused as V staging for which==2

    __half* Vst = (__half*)sm;   // [e 128][s, stride 132] fp16
    const int b = row_base / S_DIM, s_in = row_base % S_DIM, kt = s_in >> 7;
    const size_t tbase = (size_t)(b * 64 + kt) * 2048;

    #pragma unroll
    for (int jg = 0; jg < 4; ++jg) {
        float f4[4][4];
        #pragma unroll
        for (int jl = 0; jl < 4; ++jl)
            #pragma unroll
            for (int q = 0; q < 4; ++q) f4[jl][q] = 0.0f;

        #pragma unroll
        for (int jl = 0; jl < 4; ++jl) {
            const int jn = 4 * jg + jl;
            #pragma unroll
            for (int kkp = 0; kkp < 4; ++kkp) {
                uint4 bv = Wf[(jn * 4 + kkp) * 32 + lane];
                uint32_t b0[2] = {bv.x, bv.y}, b1[2] = {bv.z, bv.w};
                mma_f16(f4[jl], Xa[2 * kkp], b0);
                mma_f16(f4[jl], Xa[2 * kkp + 1], b1);
            }
            const float2 bias = *(const float2*)&bb[8 * jn + 2 * cc];
            f4[jl][0] += bias.x; f4[jl][1] += bias.y;
            f4[jl][2] += bias.x; f4[jl][3] += bias.y;
        }

        if (which == 0) {
            #pragma unroll
            for (int jl = 0; jl < 4; ++jl)
                #pragma unroll
                for (int q = 0; q < 4; ++q) f4[jl][q] *= kscale;
            const size_t mbase = ((size_t)(row_base >> 4) + (size_t)wid) * 256;
            uint4 v0, v1;
            v0.x = pack_h2(f4[0][0], f4[0][1]);
            v0.y = pack_h2(f4[0][2], f4[0][3]);
            v0.z = pack_h2(f4[1][0], f4[1][1]);
            v0.w = pack_h2(f4[1][2], f4[1][3]);
            g_Qp[mbase + (size_t)(2 * jg) * 32 + lane] = v0;
            v1.x = pack_h2(f4[2][0], f4[2][1]);
            v1.y = pack_h2(f4[2][2], f4[2][3]);
            v1.z = pack_h2(f4[3][0], f4[3][1]);
            v1.w = pack_h2(f4[3][2], f4[3][3]);
            g_Qp[mbase + (size_t)(2 * jg + 1) * 32 + lane] = v1;
        } else if (which == 1) {
            uint4 v0, v1;
            v0.x = pack_h2(f4[0][0], f4[0][1]);
            v0.y = pack_h2(f4[1][0], f4[1][1]);
            v0.z = pack_h2(f4[2][0], f4[2][1]);
            v0.w = pack_h2(f4[3][0], f4[3][1]);
            g_Kp[tbase + (size_t)(2 * wid) * 128 + jg * 32 + lane] = v0;
            v1.x = pack_h2(f4[0][2], f4[0][3]);
            v1.y = pack_h2(f4[1][2], f4[1][3]);
            v1.z = pack_h2(f4[2][2], f4[2][3]);
            v1.w = pack_h2(f4[3][2], f4[3][3]);
            g_Kp[tbase + (size_t)(2 * wid + 1) * 128 + jg * 32 + lane] = v1;
        } else {
            #pragma unroll
            for (int jl = 0; jl < 4; ++jl) {
                const int e0 = 8 * (4 * jg + jl) + 2 * cc;
                Vst[e0 * 132 + r0]           = __float2half_rn(f4[jl][0]);
                Vst[(e0 + 1) * 132 + r0]     = __float2half_rn(f4[jl][1]);
                Vst[e0 * 132 + r0 + 8]       = __float2half_rn(f4[jl][2]);
                Vst[(e0 + 1) * 132 + r0 + 8] = __float2half_rn(f4[jl][3]);
            }
        }
    }

    if (which == 2) {
        __syncthreads();
        #pragma unroll
        for (int jj = 0; jj < 2; ++jj) {
            const int j = 2 * wid + jj;
            const int erow = 8 * j + rr;
            #pragma unroll
            for (int kkp = 0; kkp < 4; ++kkp) {
                const int s0 = 32 * kkp + 2 * cc;
                const int s1 = s0 + 16;
                uint4 v;
                v.x = *(const uint32_t*)&Vst[erow * 132 + s0];
                v.y = *(const uint32_t*)&Vst[erow * 132 + s0 + 8];
                v.z = *(const uint32_t*)&Vst[erow * 132 + s1];
                v.w = *(const uint32_t*)&Vst[erow * 132 + s1 + 8];
                g_Vp[tbase + (size_t)j * 128 + kkp * 32 + lane] = v;
            }
        }
    }
}

// ============ fp16 flash attention: 3-stage pipeline, 1 sync/tile =========
// grid (S/128, B), 256 threads = 8 warps; warp w owns m-tile w (16 q rows) x
// all 128 kv columns. Q in registers, P in registers, rsum on tensor pipe.
// Pipeline (cutlass-style): wait_group(1); sync; prefetch(t+2); compute(t).
// Stage s buffer: uint4 sbuf[s*4096 .. +4096): K[0,2048) V[2048,4096).
__device__ __forceinline__ void prefetch_tile(uint32_t sdst, const uint4* ksrc,
                                              const uint4* vsrc, int t) {
    #pragma unroll
    for (int i = 0; i < 8; ++i) {
        const int s = t + i * 256;
        cp_async16(sdst + s * 16, ksrc + s);
        cp_async16(sdst + 32768 + s * 16, vsrc + s);
    }
}

__global__ __launch_bounds__(256, 1) void attn_mma_kernel(float* __restrict__ out)
{
    extern __shared__ uint4 sbuf[];   // 3 stages x 4096 uint4
    const int t = threadIdx.x;
    const int lane = t & 31, wid = t >> 5;
    const int rr = lane >> 2, cc = lane & 3;
    const int b = blockIdx.y, q0 = blockIdx.x * 128;
    const uint32_t sb = smem_to_u32(sbuf);

    // ---- Q A-frags into registers (loop-invariant) ----
    uint32_t Qa[8][4];
    {
        const uint4* qsrc = &g_Qp[(((size_t)(b * S_DIM + q0) >> 4) + (size_t)wid) * 256];
        #pragma unroll
        for (int kk = 0; kk < 8; ++kk) {
            uint4 v = qsrc[kk * 32 + lane];
            Qa[kk][0] = v.x; Qa[kk][1] = v.y; Qa[kk][2] = v.z; Qa[kk][3] = v.w;
        }
    }

    float oacc[16][4];
    #pragma unroll
    for (int j = 0; j < 16; ++j)
        #pragma unroll
        for (int q = 0; q < 4; ++q) oacc[j][q] = 0.0f;

    // rsum on tensor pipe: oe = P @ ones (n-col 0 of a virtual tile)
    float oe[4] = {0.0f, 0.0f, 0.0f, 0.0f};
    const uint32_t onesc = (rr == 0) ? 0x3C003C00u : 0u;
    uint32_t bOnes[2] = {onesc, onesc};

    const uint4* kbase = &g_Kp[(size_t)(b * 64) * 2048];
    const uint4* vbase = &g_Vp[(size_t)(b * 64) * 2048];

    // ---- prologue: tiles 0,1 into stages 0,1 ----
    prefetch_tile(sb, kbase, vbase, t);
    CP_COMMIT();
    prefetch_tile(sb + 65536, kbase + 2048, vbase + 2048, t);
    CP_COMMIT();

    int st = 0, stn = 2;   // stage of tile kt; stage for tile kt+2
    for (int kt = 0; kt < 64; ++kt) {
        CP_WAIT1();        // all but newest group done -> tile kt landed
        __syncthreads();   // visibility + overwrite-protection for stage stn

        if (kt < 62)
            prefetch_tile(sb + stn * 65536,
                          kbase + (size_t)(kt + 2) * 2048,
                          vbase + (size_t)(kt + 2) * 2048, t);
        CP_COMMIT();       // commit even when empty: keeps group counting fixed

        const uint4* Ks = sbuf + st * 4096;
        const uint4* Vs = Ks + 2048;

        #pragma unroll
        for (int kkp = 0; kkp < 4; ++kkp) {   // kv chunk: cols 32kkp..32kkp+31
            float f4[4][4];
            #pragma unroll
            for (int jl = 0; jl < 4; ++jl)
                #pragma unroll
                for (int q = 0; q < 4; ++q) f4[jl][q] = 0.0f;

            #pragma unroll
            for (int jl = 0; jl < 4; ++jl) {
                const int j = 4 * kkp + jl;
                #pragma unroll
                for (int ke = 0; ke < 4; ++ke) {
                    uint4 bv = Ks[j * 128 + ke * 32 + lane];
                    uint32_t b0[2] = {bv.x, bv.y}, b1[2] = {bv.z, bv.w};
                    mma_f16(f4[jl], Qa[2 * ke], b0);
                    mma_f16(f4[jl], Qa[2 * ke + 1], b1);
                }
            }

            uint32_t ph[4][2];
            #pragma unroll
            for (int jl = 0; jl < 4; ++jl) {
                ph[jl][0] = ex2_h2(f4[jl][0], f4[jl][1]);
                ph[jl][1] = ex2_h2(f4[jl][2], f4[jl][3]);
            }
            uint32_t a0[4] = {ph[0][0], ph[0][1], ph[1][0], ph[1][1]};
            uint32_t a1[4] = {ph[2][0], ph[2][1], ph[3][0], ph[3][1]};

            mma_f16(oe, a0, bOnes);
            mma_f16(oe, a1, bOnes);
            #pragma unroll
            for (int je = 0; je < 16; ++je) {
                uint4 bv = Vs[je * 128 + kkp * 32 + lane];
                uint32_t b0[2] = {bv.x, bv.y}, b1[2] = {bv.z, bv.w};
                mma_f16(oacc[je], a0, b0);
                mma_f16(oacc[je], a1, b1);
            }
        }

        st  = (st  == 2) ? 0 : st + 1;
        stn = (stn == 2) ? 0 : stn + 1;
    }

    // ---- row sums in oe[0]/oe[2] of cc==0 lanes; broadcast to quad ----
    const float s0 = __shfl_sync(0xffffffffu, oe[0], lane & 28);
    const float s1 = __shfl_sync(0xffffffffu, oe[2], lane & 28);
    const float inv0 = 1.0f / s0;
    const float inv1 = 1.0f / s1;

    const size_t row0 = (size_t)b * S_DIM + q0 + 16 * wid + rr;
    #pragma unroll
    for (int j = 0; j < 16; ++j) {
        const int e = 8 * j + 2 * cc;
        *(float2*)&out[row0 * E_DIM + e] =
            make_float2(oacc[j][0] * inv0, oacc[j][1] * inv0);
        *(float2*)&out[(row0 + 8) * E_DIM + e] =
            make_float2(oacc[j][2] * inv1, oacc[j][3] * inv1);
    }
}

// ============================== launch =====================================
extern "C" void kernel_launch(void* const* d_in, const int* in_sizes, int n_in,
                              void* d_out, int out_size)
{
    (void)in_sizes; (void)n_in; (void)out_size;
    const float* x  = (const float*)d_in[0];
    const float* Wq = (const float*)d_in[1];
    const float* bq = (const float*)d_in[2];
    const float* Wk = (const float*)d_in[3];
    const float* bk = (const float*)d_in[4];
    const float* Wv = (const float*)d_in[5];
    const float* bv = (const float*)d_in[6];
    float* out = (float*)d_out;

    const int proj_smem = 128 * 132 * 4 + 2048 * 16;   // 100352 B
    const int attn_smem = 3 * 65536;                    // 196608 B

    cudaFuncSetAttribute(proj_kernel, cudaFuncAttributeMaxDynamicSharedMemorySize, proj_smem);
    cudaFuncSetAttribute(attn_mma_kernel, cudaFuncAttributeMaxDynamicSharedMemorySize, attn_smem);

    dim3 pg((B_DIM * S_DIM) / 128, 3);
    proj_kernel<<<pg, 256, proj_smem>>>(x, Wq, bq, Wk, bk, Wv, bv);

    dim3 ag(S_DIM / 128, B_DIM);
    attn_mma_kernel<<<ag, 256, attn_smem>>>(out);
}